// round 1
// baseline (speedup 1.0000x reference)
#include <cuda_runtime.h>
#include <math.h>

// ---------------------------------------------------------------------------
// S2Attention: B=8, C=512, H=W=64, HEADS=8, d=64, R=4 -> kv tokens 17x17=289
//
// Pipeline (all fp32, round-1 correctness-focused):
//   1. q   = wq @ sem                 (GEMM, scale 0.125 folded in)
//   2. kpre= LN(dwconv(spa)), vpre = LN(dwconv(x))
//   3. k   = wkv_pw @ kpre, v = wkv_pw @ vpre   (GEMM, N=289)
//   4. attention per (b,h): q[4096,64] x k[289,64]^T, softmax, x v[289,64]
//   5. out = wout @ attn_out          (GEMM)
//
// Layout trick: head-split [(b*8+h)][n][dc] rows == plain [b*512+c] rows,
// so every 1x1 conv is the same batched GEMM with row-major [C][N] output.
// ---------------------------------------------------------------------------

#define CC   512
#define HWQ  4096
#define NKV  289
#define NBAT 8

__device__ float g_q   [8L * 512 * 4096];   // [b*512+c][4096], pre-scaled by 0.125
__device__ float g_kpre[8L * 512 * 289];
__device__ float g_vpre[8L * 512 * 289];
__device__ float g_k   [8L * 512 * 289];    // [b*512+c][289]
__device__ float g_v   [8L * 512 * 289];
__device__ float g_ao  [8L * 512 * 4096];   // attention output, [b*512+c][4096]

// ---------------------------------------------------------------------------
// GEMM: out[(b*512+co)*N + n] = scale * sum_ci W[co*512+ci] * A[(b*512+ci)*N + n]
// Tile 128x128, K-chunk 8, 256 threads, 8x8 per-thread register tile.
// asel: 0=g_kpre 1=g_vpre 2=g_ao else Aext;  osel: 0=g_q 1=g_k 2=g_v else Oext
// ---------------------------------------------------------------------------
__global__ __launch_bounds__(256)
void gemm512(const float* __restrict__ W, const float* __restrict__ Aext,
             float* __restrict__ Oext, int asel, int osel, int N, float scale)
{
    const float* Abase = (asel == 0) ? g_kpre : (asel == 1) ? g_vpre
                       : (asel == 2) ? g_ao   : Aext;
    float* Obase = (osel == 0) ? g_q : (osel == 1) ? g_k
                 : (osel == 2) ? g_v : Oext;

    const int b  = blockIdx.z;
    const int n0 = blockIdx.x * 128;
    const int m0 = blockIdx.y * 128;
    const float* A = Abase + (long)b * 512 * N;

    __shared__ float Ws[8][128];
    __shared__ float As[8][128];

    const int t  = threadIdx.x;
    const int tx = t & 15;        // n direction
    const int ty = t >> 4;        // m direction

    float acc[8][8];
#pragma unroll
    for (int i = 0; i < 8; i++)
#pragma unroll
        for (int j = 0; j < 8; j++) acc[i][j] = 0.f;

    for (int k0 = 0; k0 < 512; k0 += 8) {
        // W tile: 128 rows x 8 k, one float4 per thread
        {
            int m  = t >> 1;
            int k4 = (t & 1) * 4;
            float4 w4 = *reinterpret_cast<const float4*>(&W[(m0 + m) * 512 + k0 + k4]);
            Ws[k4 + 0][m] = w4.x; Ws[k4 + 1][m] = w4.y;
            Ws[k4 + 2][m] = w4.z; Ws[k4 + 3][m] = w4.w;
        }
        // A tile: 8 k x 128 n, scalar (N=289 rows are not 16B aligned)
        {
            int kk = t >> 5;
            int nb = (t & 31) * 4;
            const float* arow = &A[(long)(k0 + kk) * N];
#pragma unroll
            for (int u = 0; u < 4; u++) {
                int n = n0 + nb + u;
                As[kk][nb + u] = (n < N) ? arow[n] : 0.f;
            }
        }
        __syncthreads();

#pragma unroll
        for (int kk = 0; kk < 8; kk++) {
            float4 w0 = *reinterpret_cast<const float4*>(&Ws[kk][ty * 8]);
            float4 w1 = *reinterpret_cast<const float4*>(&Ws[kk][ty * 8 + 4]);
            float4 a0 = *reinterpret_cast<const float4*>(&As[kk][tx * 8]);
            float4 a1 = *reinterpret_cast<const float4*>(&As[kk][tx * 8 + 4]);
            float wr[8] = {w0.x, w0.y, w0.z, w0.w, w1.x, w1.y, w1.z, w1.w};
            float ar[8] = {a0.x, a0.y, a0.z, a0.w, a1.x, a1.y, a1.z, a1.w};
#pragma unroll
            for (int i = 0; i < 8; i++)
#pragma unroll
                for (int j = 0; j < 8; j++)
                    acc[i][j] = fmaf(wr[i], ar[j], acc[i][j]);
        }
        __syncthreads();
    }

    // epilogue: row-major [co][n] (coalesced along n)
#pragma unroll
    for (int i = 0; i < 8; i++) {
        int co = m0 + ty * 8 + i;
        float* orow = &Obase[((long)b * 512 + co) * N];
#pragma unroll
        for (int j = 0; j < 8; j++) {
            int n = n0 + tx * 8 + j;
            if (n < N) orow[n] = acc[i][j] * scale;
        }
    }
}

// ---------------------------------------------------------------------------
// Depthwise 4x4 stride-4 pad-2 conv + channel LayerNorm (biased var).
// grid (289, 8), block 512 (one thread per channel).
// osel: 0 -> g_kpre, 1 -> g_vpre
// ---------------------------------------------------------------------------
__global__ __launch_bounds__(512)
void dwln_kernel(const float* __restrict__ in, const float* __restrict__ wdw,
                 const float* __restrict__ lng, const float* __restrict__ lnb,
                 int osel)
{
    float* out = osel ? g_vpre : g_kpre;
    const int pos = blockIdx.x;       // 0..288
    const int b   = blockIdx.y;
    const int c   = threadIdx.x;      // 0..511
    const int oy = pos / 17, ox = pos % 17;

    const float* ip = in + ((long)b * 512 + c) * 4096;
    const float* wp = wdw + c * 16;

    float acc = 0.f;
#pragma unroll
    for (int ky = 0; ky < 4; ky++) {
        int y = oy * 4 - 2 + ky;
        if ((unsigned)y < 64u) {
#pragma unroll
            for (int kx = 0; kx < 4; kx++) {
                int xx = ox * 4 - 2 + kx;
                if ((unsigned)xx < 64u)
                    acc = fmaf(wp[ky * 4 + kx], ip[y * 64 + xx], acc);
            }
        }
    }

    // block reduce sum & sumsq over 512 channels
    __shared__ float s1[16], s2[16];
    float v1 = acc, v2 = acc * acc;
#pragma unroll
    for (int o = 16; o > 0; o >>= 1) {
        v1 += __shfl_xor_sync(0xffffffffu, v1, o);
        v2 += __shfl_xor_sync(0xffffffffu, v2, o);
    }
    int w = threadIdx.x >> 5, lane = threadIdx.x & 31;
    if (lane == 0) { s1[w] = v1; s2[w] = v2; }
    __syncthreads();
    if (w == 0) {
        v1 = (lane < 16) ? s1[lane] : 0.f;
        v2 = (lane < 16) ? s2[lane] : 0.f;
#pragma unroll
        for (int o = 8; o > 0; o >>= 1) {
            v1 += __shfl_xor_sync(0xffffffffu, v1, o);
            v2 += __shfl_xor_sync(0xffffffffu, v2, o);
        }
        if (lane == 0) { s1[0] = v1; s2[0] = v2; }
    }
    __syncthreads();
    float mean = s1[0] * (1.f / 512.f);
    float var  = s2[0] * (1.f / 512.f) - mean * mean;
    float r    = rsqrtf(var + 1e-5f);
    out[((long)b * 512 + c) * 289 + pos] = (acc - mean) * r * lng[c] + lnb[c];
}

// ---------------------------------------------------------------------------
// Attention: per (bh, q-tile of 32 rows). Nk=289, d=64.
// K, V, Q, scores all in dynamic SMEM (~195 KB). q already scaled by 0.125.
// grid (128, 64), block 256.
// ---------------------------------------------------------------------------
#define SC_STRIDE 296   // 32*296 scores, picked so writes are conflict-free
#define ATTN_SMEM ((289 * 65 + 289 * 64 + 32 * 65 + 32 * SC_STRIDE) * 4)

__global__ __launch_bounds__(256)
void attn_kernel()
{
    extern __shared__ float sm[];
    float* Ks = sm;                      // [289][65] padded
    float* Vs = Ks + 289 * 65;           // [289][64]
    float* Qs = Vs + 289 * 64;           // [32][65] padded
    float* Sc = Qs + 32 * 65;            // [32][296]

    const int bh = blockIdx.y;           // 0..63 == b*8+h
    const int n0 = blockIdx.x * 32;
    const int t  = threadIdx.x;

    const float* kb = g_k + (long)bh * 64 * 289;    // [dc][289]
    const float* vb = g_v + (long)bh * 64 * 289;
    const float* qb = g_q + (long)bh * 64 * 4096;   // [dc][4096]

    // load K,V (transpose [dc][j] -> smem [j][dc]); coalesced global reads
    for (int idx = t; idx < 64 * 289; idx += 256) {
        int dc = idx / 289;
        int j  = idx - dc * 289;
        float kv = kb[dc * 289 + j];
        float vv = vb[dc * 289 + j];
        Ks[j * 65 + dc] = kv;
        Vs[j * 64 + dc] = vv;
    }
    // load Q tile: [dc][n] -> smem [nn][dc]
    for (int idx = t; idx < 32 * 64; idx += 256) {
        int nn = idx & 31, dc = idx >> 5;
        Qs[nn * 65 + dc] = qb[(long)dc * 4096 + n0 + nn];
    }
    __syncthreads();

    // ---- scores: 8 threads per q row, 37 j-slots per thread ----
    const int row  = t >> 3;   // 0..31
    const int tsub = t & 7;

    float acc[37];
#pragma unroll
    for (int i = 0; i < 37; i++) acc[i] = 0.f;

    for (int dc0 = 0; dc0 < 64; dc0 += 8) {
        float qr[8];
#pragma unroll
        for (int u = 0; u < 8; u++) qr[u] = Qs[row * 65 + dc0 + u];
#pragma unroll
        for (int i = 0; i < 37; i++) {
            int j = tsub + i * 8;
            if (j < NKV) {
                const float* kp = &Ks[j * 65 + dc0];
                float a = acc[i];
#pragma unroll
                for (int u = 0; u < 8; u++) a = fmaf(qr[u], kp[u], a);
                acc[i] = a;
            }
        }
    }

    // ---- softmax across the 8-thread group (lanes are 8-aligned in warp) ----
    float mx = -1e30f;
#pragma unroll
    for (int i = 0; i < 37; i++) {
        int j = tsub + i * 8;
        if (j < NKV) mx = fmaxf(mx, acc[i]);
    }
#pragma unroll
    for (int o = 4; o > 0; o >>= 1) mx = fmaxf(mx, __shfl_xor_sync(0xffffffffu, mx, o));

    float sum = 0.f;
#pragma unroll
    for (int i = 0; i < 37; i++) {
        int j = tsub + i * 8;
        if (j < NKV) {
            float e = __expf(acc[i] - mx);
            acc[i] = e;
            sum += e;
        }
    }
#pragma unroll
    for (int o = 4; o > 0; o >>= 1) sum += __shfl_xor_sync(0xffffffffu, sum, o);
    float inv = 1.f / sum;

#pragma unroll
    for (int i = 0; i < 37; i++) {
        int j = tsub + i * 8;
        if (j < NKV) Sc[row * SC_STRIDE + j] = acc[i] * inv;
    }
    __syncthreads();

    // ---- attn @ V: thread t handles dc=t&63, rows rg*8..rg*8+7 ----
    const int dc = t & 63;
    const int rg = t >> 6;   // 0..3
    float o[8];
#pragma unroll
    for (int r = 0; r < 8; r++) o[r] = 0.f;

    for (int j = 0; j < NKV; j++) {
        float vv = Vs[j * 64 + dc];
#pragma unroll
        for (int r = 0; r < 8; r++)
            o[r] = fmaf(Sc[(rg * 8 + r) * SC_STRIDE + j], vv, o[r]);
    }

    // stage through smem (reuse Ks) for coalesced [c][n] global writes
    float* stage = Ks;   // [64][33]
#pragma unroll
    for (int r = 0; r < 8; r++) stage[dc * 33 + rg * 8 + r] = o[r];
    __syncthreads();

    for (int idx = t; idx < 64 * 32; idx += 256) {
        int nn = idx & 31, d2 = idx >> 5;
        g_ao[((long)bh * 64 + d2) * 4096 + n0 + nn] = stage[d2 * 33 + nn];
    }
}

// ---------------------------------------------------------------------------
// launcher
// ---------------------------------------------------------------------------
extern "C" void kernel_launch(void* const* d_in, const int* in_sizes, int n_in,
                              void* d_out, int out_size)
{
    const float* sem  = (const float*)d_in[0];
    const float* spa  = (const float*)d_in[1];
    const float* x    = (const float*)d_in[2];
    const float* wq   = (const float*)d_in[3];
    const float* wdw  = (const float*)d_in[4];
    const float* lng  = (const float*)d_in[5];
    const float* lnb  = (const float*)d_in[6];
    const float* wpw  = (const float*)d_in[7];
    const float* wout = (const float*)d_in[8];
    float* out = (float*)d_out;

    cudaFuncSetAttribute(attn_kernel,
                         cudaFuncAttributeMaxDynamicSharedMemorySize, ATTN_SMEM);

    const float scale = 0.125f;  // (C/HEADS)^-0.5 = 64^-0.5

    // 1. q projection (scale folded in), out -> g_q
    gemm512<<<dim3(32, 4, 8), 256>>>(wq, sem, nullptr, /*asel*/3, /*osel*/0,
                                     HWQ, scale);
    // 2. depthwise conv + LN
    dwln_kernel<<<dim3(289, 8), 512>>>(spa, wdw, lng, lnb, 0);
    dwln_kernel<<<dim3(289, 8), 512>>>(x,   wdw, lng, lnb, 1);
    // 3. pointwise convs -> k, v
    gemm512<<<dim3(3, 4, 8), 256>>>(wpw, nullptr, nullptr, 0, 1, NKV, 1.f);
    gemm512<<<dim3(3, 4, 8), 256>>>(wpw, nullptr, nullptr, 1, 2, NKV, 1.f);
    // 4. attention
    attn_kernel<<<dim3(128, 64), 256, ATTN_SMEM>>>();
    // 5. output projection -> d_out
    gemm512<<<dim3(32, 4, 8), 256>>>(wout, nullptr, out, 2, 3, HWQ, 1.f);
}

// round 2
// speedup vs baseline: 1.0019x; 1.0019x over previous
#include <cuda_runtime.h>
#include <math.h>

// ---------------------------------------------------------------------------
// S2Attention: B=8, C=512, H=W=64, HEADS=8, d=64, R=4 -> kv tokens 17x17=289
//
// Pipeline (all fp32, round-1 correctness-focused):
//   1. q   = wq @ sem                 (GEMM, scale 0.125 folded in)
//   2. kpre= LN(dwconv(spa)), vpre = LN(dwconv(x))
//   3. k   = wkv_pw @ kpre, v = wkv_pw @ vpre   (GEMM, N=289)
//   4. attention per (b,h): q[4096,64] x k[289,64]^T, softmax, x v[289,64]
//   5. out = wout @ attn_out          (GEMM)
//
// Layout trick: head-split [(b*8+h)][n][dc] rows == plain [b*512+c] rows,
// so every 1x1 conv is the same batched GEMM with row-major [C][N] output.
// ---------------------------------------------------------------------------

#define CC   512
#define HWQ  4096
#define NKV  289
#define NBAT 8

__device__ float g_q   [8L * 512 * 4096];   // [b*512+c][4096], pre-scaled by 0.125
__device__ float g_kpre[8L * 512 * 289];
__device__ float g_vpre[8L * 512 * 289];
__device__ float g_k   [8L * 512 * 289];    // [b*512+c][289]
__device__ float g_v   [8L * 512 * 289];
__device__ float g_ao  [8L * 512 * 4096];   // attention output, [b*512+c][4096]

// ---------------------------------------------------------------------------
// GEMM: out[(b*512+co)*N + n] = scale * sum_ci W[co*512+ci] * A[(b*512+ci)*N + n]
// Tile 128x128, K-chunk 8, 256 threads, 8x8 per-thread register tile.
// asel: 0=g_kpre 1=g_vpre 2=g_ao else Aext;  osel: 0=g_q 1=g_k 2=g_v else Oext
// ---------------------------------------------------------------------------
__global__ __launch_bounds__(256)
void gemm512(const float* __restrict__ W, const float* __restrict__ Aext,
             float* __restrict__ Oext, int asel, int osel, int N, float scale)
{
    const float* Abase = (asel == 0) ? g_kpre : (asel == 1) ? g_vpre
                       : (asel == 2) ? g_ao   : Aext;
    float* Obase = (osel == 0) ? g_q : (osel == 1) ? g_k
                 : (osel == 2) ? g_v : Oext;

    const int b  = blockIdx.z;
    const int n0 = blockIdx.x * 128;
    const int m0 = blockIdx.y * 128;
    const float* A = Abase + (long)b * 512 * N;

    __shared__ float Ws[8][128];
    __shared__ float As[8][128];

    const int t  = threadIdx.x;
    const int tx = t & 15;        // n direction
    const int ty = t >> 4;        // m direction

    float acc[8][8];
#pragma unroll
    for (int i = 0; i < 8; i++)
#pragma unroll
        for (int j = 0; j < 8; j++) acc[i][j] = 0.f;

    for (int k0 = 0; k0 < 512; k0 += 8) {
        // W tile: 128 rows x 8 k, one float4 per thread
        {
            int m  = t >> 1;
            int k4 = (t & 1) * 4;
            float4 w4 = *reinterpret_cast<const float4*>(&W[(m0 + m) * 512 + k0 + k4]);
            Ws[k4 + 0][m] = w4.x; Ws[k4 + 1][m] = w4.y;
            Ws[k4 + 2][m] = w4.z; Ws[k4 + 3][m] = w4.w;
        }
        // A tile: 8 k x 128 n, scalar (N=289 rows are not 16B aligned)
        {
            int kk = t >> 5;
            int nb = (t & 31) * 4;
            const float* arow = &A[(long)(k0 + kk) * N];
#pragma unroll
            for (int u = 0; u < 4; u++) {
                int n = n0 + nb + u;
                As[kk][nb + u] = (n < N) ? arow[n] : 0.f;
            }
        }
        __syncthreads();

#pragma unroll
        for (int kk = 0; kk < 8; kk++) {
            float4 w0 = *reinterpret_cast<const float4*>(&Ws[kk][ty * 8]);
            float4 w1 = *reinterpret_cast<const float4*>(&Ws[kk][ty * 8 + 4]);
            float4 a0 = *reinterpret_cast<const float4*>(&As[kk][tx * 8]);
            float4 a1 = *reinterpret_cast<const float4*>(&As[kk][tx * 8 + 4]);
            float wr[8] = {w0.x, w0.y, w0.z, w0.w, w1.x, w1.y, w1.z, w1.w};
            float ar[8] = {a0.x, a0.y, a0.z, a0.w, a1.x, a1.y, a1.z, a1.w};
#pragma unroll
            for (int i = 0; i < 8; i++)
#pragma unroll
                for (int j = 0; j < 8; j++)
                    acc[i][j] = fmaf(wr[i], ar[j], acc[i][j]);
        }
        __syncthreads();
    }

    // epilogue: row-major [co][n] (coalesced along n)
#pragma unroll
    for (int i = 0; i < 8; i++) {
        int co = m0 + ty * 8 + i;
        float* orow = &Obase[((long)b * 512 + co) * N];
#pragma unroll
        for (int j = 0; j < 8; j++) {
            int n = n0 + tx * 8 + j;
            if (n < N) orow[n] = acc[i][j] * scale;
        }
    }
}

// ---------------------------------------------------------------------------
// Depthwise 4x4 stride-4 pad-2 conv + channel LayerNorm (biased var).
// grid (289, 8), block 512 (one thread per channel).
// osel: 0 -> g_kpre, 1 -> g_vpre
// ---------------------------------------------------------------------------
__global__ __launch_bounds__(512)
void dwln_kernel(const float* __restrict__ in, const float* __restrict__ wdw,
                 const float* __restrict__ lng, const float* __restrict__ lnb,
                 int osel)
{
    float* out = osel ? g_vpre : g_kpre;
    const int pos = blockIdx.x;       // 0..288
    const int b   = blockIdx.y;
    const int c   = threadIdx.x;      // 0..511
    const int oy = pos / 17, ox = pos % 17;

    const float* ip = in + ((long)b * 512 + c) * 4096;
    const float* wp = wdw + c * 16;

    float acc = 0.f;
#pragma unroll
    for (int ky = 0; ky < 4; ky++) {
        int y = oy * 4 - 2 + ky;
        if ((unsigned)y < 64u) {
#pragma unroll
            for (int kx = 0; kx < 4; kx++) {
                int xx = ox * 4 - 2 + kx;
                if ((unsigned)xx < 64u)
                    acc = fmaf(wp[ky * 4 + kx], ip[y * 64 + xx], acc);
            }
        }
    }

    // block reduce sum & sumsq over 512 channels
    __shared__ float s1[16], s2[16];
    float v1 = acc, v2 = acc * acc;
#pragma unroll
    for (int o = 16; o > 0; o >>= 1) {
        v1 += __shfl_xor_sync(0xffffffffu, v1, o);
        v2 += __shfl_xor_sync(0xffffffffu, v2, o);
    }
    int w = threadIdx.x >> 5, lane = threadIdx.x & 31;
    if (lane == 0) { s1[w] = v1; s2[w] = v2; }
    __syncthreads();
    if (w == 0) {
        v1 = (lane < 16) ? s1[lane] : 0.f;
        v2 = (lane < 16) ? s2[lane] : 0.f;
#pragma unroll
        for (int o = 8; o > 0; o >>= 1) {
            v1 += __shfl_xor_sync(0xffffffffu, v1, o);
            v2 += __shfl_xor_sync(0xffffffffu, v2, o);
        }
        if (lane == 0) { s1[0] = v1; s2[0] = v2; }
    }
    __syncthreads();
    float mean = s1[0] * (1.f / 512.f);
    float var  = s2[0] * (1.f / 512.f) - mean * mean;
    float r    = rsqrtf(var + 1e-5f);
    out[((long)b * 512 + c) * 289 + pos] = (acc - mean) * r * lng[c] + lnb[c];
}

// ---------------------------------------------------------------------------
// Attention: per (bh, q-tile of 32 rows). Nk=289, d=64.
// K, V, Q, scores all in dynamic SMEM (~195 KB). q already scaled by 0.125.
// grid (128, 64), block 256.
// ---------------------------------------------------------------------------
#define SC_STRIDE 296   // 32*296 scores, picked so writes are conflict-free
#define ATTN_SMEM ((289 * 65 + 289 * 64 + 32 * 65 + 32 * SC_STRIDE) * 4)

__global__ __launch_bounds__(256)
void attn_kernel()
{
    extern __shared__ float sm[];
    float* Ks = sm;                      // [289][65] padded
    float* Vs = Ks + 289 * 65;           // [289][64]
    float* Qs = Vs + 289 * 64;           // [32][65] padded
    float* Sc = Qs + 32 * 65;            // [32][296]

    const int bh = blockIdx.y;           // 0..63 == b*8+h
    const int n0 = blockIdx.x * 32;
    const int t  = threadIdx.x;

    const float* kb = g_k + (long)bh * 64 * 289;    // [dc][289]
    const float* vb = g_v + (long)bh * 64 * 289;
    const float* qb = g_q + (long)bh * 64 * 4096;   // [dc][4096]

    // load K,V (transpose [dc][j] -> smem [j][dc]); coalesced global reads
    for (int idx = t; idx < 64 * 289; idx += 256) {
        int dc = idx / 289;
        int j  = idx - dc * 289;
        float kv = kb[dc * 289 + j];
        float vv = vb[dc * 289 + j];
        Ks[j * 65 + dc] = kv;
        Vs[j * 64 + dc] = vv;
    }
    // load Q tile: [dc][n] -> smem [nn][dc]
    for (int idx = t; idx < 32 * 64; idx += 256) {
        int nn = idx & 31, dc = idx >> 5;
        Qs[nn * 65 + dc] = qb[(long)dc * 4096 + n0 + nn];
    }
    __syncthreads();

    // ---- scores: 8 threads per q row, 37 j-slots per thread ----
    const int row  = t >> 3;   // 0..31
    const int tsub = t & 7;

    float acc[37];
#pragma unroll
    for (int i = 0; i < 37; i++) acc[i] = 0.f;

    for (int dc0 = 0; dc0 < 64; dc0 += 8) {
        float qr[8];
#pragma unroll
        for (int u = 0; u < 8; u++) qr[u] = Qs[row * 65 + dc0 + u];
#pragma unroll
        for (int i = 0; i < 37; i++) {
            int j = tsub + i * 8;
            if (j < NKV) {
                const float* kp = &Ks[j * 65 + dc0];
                float a = acc[i];
#pragma unroll
                for (int u = 0; u < 8; u++) a = fmaf(qr[u], kp[u], a);
                acc[i] = a;
            }
        }
    }

    // ---- softmax across the 8-thread group (lanes are 8-aligned in warp) ----
    float mx = -1e30f;
#pragma unroll
    for (int i = 0; i < 37; i++) {
        int j = tsub + i * 8;
        if (j < NKV) mx = fmaxf(mx, acc[i]);
    }
#pragma unroll
    for (int o = 4; o > 0; o >>= 1) mx = fmaxf(mx, __shfl_xor_sync(0xffffffffu, mx, o));

    float sum = 0.f;
#pragma unroll
    for (int i = 0; i < 37; i++) {
        int j = tsub + i * 8;
        if (j < NKV) {
            float e = __expf(acc[i] - mx);
            acc[i] = e;
            sum += e;
        }
    }
#pragma unroll
    for (int o = 4; o > 0; o >>= 1) sum += __shfl_xor_sync(0xffffffffu, sum, o);
    float inv = 1.f / sum;

#pragma unroll
    for (int i = 0; i < 37; i++) {
        int j = tsub + i * 8;
        if (j < NKV) Sc[row * SC_STRIDE + j] = acc[i] * inv;
    }
    __syncthreads();

    // ---- attn @ V: thread t handles dc=t&63, rows rg*8..rg*8+7 ----
    const int dc = t & 63;
    const int rg = t >> 6;   // 0..3
    float o[8];
#pragma unroll
    for (int r = 0; r < 8; r++) o[r] = 0.f;

    for (int j = 0; j < NKV; j++) {
        float vv = Vs[j * 64 + dc];
#pragma unroll
        for (int r = 0; r < 8; r++)
            o[r] = fmaf(Sc[(rg * 8 + r) * SC_STRIDE + j], vv, o[r]);
    }

    // stage through smem (reuse Ks) for coalesced [c][n] global writes
    float* stage = Ks;   // [64][33]
#pragma unroll
    for (int r = 0; r < 8; r++) stage[dc * 33 + rg * 8 + r] = o[r];
    __syncthreads();

    for (int idx = t; idx < 64 * 32; idx += 256) {
        int nn = idx & 31, d2 = idx >> 5;
        g_ao[((long)bh * 64 + d2) * 4096 + n0 + nn] = stage[d2 * 33 + nn];
    }
}

// ---------------------------------------------------------------------------
// launcher
// ---------------------------------------------------------------------------
extern "C" void kernel_launch(void* const* d_in, const int* in_sizes, int n_in,
                              void* d_out, int out_size)
{
    const float* sem  = (const float*)d_in[0];
    const float* spa  = (const float*)d_in[1];
    const float* x    = (const float*)d_in[2];
    const float* wq   = (const float*)d_in[3];
    const float* wdw  = (const float*)d_in[4];
    const float* lng  = (const float*)d_in[5];
    const float* lnb  = (const float*)d_in[6];
    const float* wpw  = (const float*)d_in[7];
    const float* wout = (const float*)d_in[8];
    float* out = (float*)d_out;

    cudaFuncSetAttribute(attn_kernel,
                         cudaFuncAttributeMaxDynamicSharedMemorySize, ATTN_SMEM);

    const float scale = 0.125f;  // (C/HEADS)^-0.5 = 64^-0.5

    // 1. q projection (scale folded in), out -> g_q
    gemm512<<<dim3(32, 4, 8), 256>>>(wq, sem, nullptr, /*asel*/3, /*osel*/0,
                                     HWQ, scale);
    // 2. depthwise conv + LN
    dwln_kernel<<<dim3(289, 8), 512>>>(spa, wdw, lng, lnb, 0);
    dwln_kernel<<<dim3(289, 8), 512>>>(x,   wdw, lng, lnb, 1);
    // 3. pointwise convs -> k, v
    gemm512<<<dim3(3, 4, 8), 256>>>(wpw, nullptr, nullptr, 0, 1, NKV, 1.f);
    gemm512<<<dim3(3, 4, 8), 256>>>(wpw, nullptr, nullptr, 1, 2, NKV, 1.f);
    // 4. attention
    attn_kernel<<<dim3(128, 64), 256, ATTN_SMEM>>>();
    // 5. output projection -> d_out
    gemm512<<<dim3(32, 4, 8), 256>>>(wout, nullptr, out, 2, 3, HWQ, 1.f);
}

// round 4
// speedup vs baseline: 1.5566x; 1.5537x over previous
#include <cuda_runtime.h>
#include <cuda_bf16.h>
#include <cstdint>
#include <math.h>

// ===========================================================================
// S2Attention on GB300 (sm_103 portable path):
//   - 1x1 convs as bf16 hi/lo mma.sync GEMMs (3 MMA passes -> fp32-accuracy)
//   - fp32 SIMT attention (known-correct structure)
// B=8, C=512, H=W=64, HEADS=8, d=64, kv tokens 17x17=289
// ===========================================================================

#define HWQ  4096
#define NKV  289

// ---------------- device scratch (token-major activations) ----------------
__device__ __align__(256) __nv_bfloat16 g_semT_hi[8L * 4096 * 512];
__device__ __align__(256) __nv_bfloat16 g_semT_lo[8L * 4096 * 512];
__device__ __align__(256) __nv_bfloat16 g_kpreT_hi[8L * 289 * 512];
__device__ __align__(256) __nv_bfloat16 g_kpreT_lo[8L * 289 * 512];
__device__ __align__(256) __nv_bfloat16 g_vpreT_hi[8L * 289 * 512];
__device__ __align__(256) __nv_bfloat16 g_vpreT_lo[8L * 289 * 512];
__device__ __align__(256) __nv_bfloat16 g_aoT_hi[8L * 4096 * 512];
__device__ __align__(256) __nv_bfloat16 g_aoT_lo[8L * 4096 * 512];
__device__ __align__(256) float g_qT[8L * 4096 * 512];   // [b][tok][c], q*0.125
__device__ __align__(256) float g_kT[8L * 289 * 512];
__device__ __align__(256) float g_vT[8L * 289 * 512];
__device__ __align__(256) __nv_bfloat16 g_whi[3L * 512 * 512]; // 0=wq*0.125,1=wpw,2=wout
__device__ __align__(256) __nv_bfloat16 g_wlo[3L * 512 * 512];

// ---------------- helpers ----------------
__device__ __forceinline__ uint32_t smem_u32(const void* p) {
    uint32_t a;
    asm("{ .reg .u64 t; cvta.to.shared.u64 t, %1; cvt.u32.u64 %0, t; }"
        : "=r"(a) : "l"(p));
    return a;
}

__device__ __forceinline__ void mma_bf16(float* d, const uint32_t* a, const uint32_t* b) {
    asm volatile(
        "mma.sync.aligned.m16n8k16.row.col.f32.bf16.bf16.f32 "
        "{%0,%1,%2,%3}, {%4,%5,%6,%7}, {%8,%9}, {%0,%1,%2,%3};"
        : "+f"(d[0]), "+f"(d[1]), "+f"(d[2]), "+f"(d[3])
        : "r"(a[0]), "r"(a[1]), "r"(a[2]), "r"(a[3]), "r"(b[0]), "r"(b[1]));
}

__device__ __forceinline__ void cpa16(uint32_t dst, const void* src, uint32_t nbytes) {
    asm volatile("cp.async.cg.shared.global [%0], [%1], 16, %2;"
                 :: "r"(dst), "l"(src), "r"(nbytes) : "memory");
}
#define CPA_COMMIT() asm volatile("cp.async.commit_group;" ::: "memory")
#define CPA_WAIT0()  asm volatile("cp.async.wait_group 0;" ::: "memory")

// ---------------------------------------------------------------------------
// prep: weights -> bf16 hi/lo (wq pre-scaled by 0.125)
// ---------------------------------------------------------------------------
__global__ void prep_w(const float* __restrict__ wq, const float* __restrict__ wpw,
                       const float* __restrict__ wout)
{
    int i = blockIdx.x * 256 + threadIdx.x;
    if (i >= 3 * 262144) return;
    int widx = i >> 18, j = i & 262143;
    float v = (widx == 0) ? wq[j] * 0.125f : (widx == 1) ? wpw[j] : wout[j];
    __nv_bfloat16 h = __float2bfloat16(v);
    g_whi[i] = h;
    g_wlo[i] = __float2bfloat16(v - __bfloat162float(h));
}

// ---------------------------------------------------------------------------
// transpose + split: sem [b][c][4096] fp32 -> g_semT hi/lo [b][tok][512]
// ---------------------------------------------------------------------------
__global__ __launch_bounds__(256)
void transpose_split(const float* __restrict__ in)
{
    __shared__ float tile[32][33];
    int b = blockIdx.z, n0 = blockIdx.x * 32, c0 = blockIdx.y * 32;
    int tx = threadIdx.x, ty = threadIdx.y;
#pragma unroll
    for (int k = 0; k < 4; k++) {
        int c = c0 + ty + 8 * k;
        tile[ty + 8 * k][tx] = in[((long)b * 512 + c) * 4096 + n0 + tx];
    }
    __syncthreads();
#pragma unroll
    for (int k = 0; k < 4; k++) {
        int n = n0 + ty + 8 * k;
        float v = tile[tx][ty + 8 * k];
        __nv_bfloat16 h = __float2bfloat16(v);
        long o = ((long)b * 4096 + n) * 512 + c0 + tx;
        g_semT_hi[o] = h;
        g_semT_lo[o] = __float2bfloat16(v - __bfloat162float(h));
    }
}

// ---------------------------------------------------------------------------
// depthwise 4x4 s4 p2 conv + channel LN -> token-major bf16 hi/lo
// grid (289, 8), block 512
// ---------------------------------------------------------------------------
__global__ __launch_bounds__(512)
void dwln_kernel(const float* __restrict__ in, const float* __restrict__ wdw,
                 const float* __restrict__ lng, const float* __restrict__ lnb,
                 int osel)
{
    __nv_bfloat16* oh = osel ? g_vpreT_hi : g_kpreT_hi;
    __nv_bfloat16* ol = osel ? g_vpreT_lo : g_kpreT_lo;
    const int pos = blockIdx.x, b = blockIdx.y, c = threadIdx.x;
    const int oy = pos / 17, ox = pos % 17;
    const float* ip = in + ((long)b * 512 + c) * 4096;
    const float* wp = wdw + c * 16;

    float acc = 0.f;
#pragma unroll
    for (int ky = 0; ky < 4; ky++) {
        int y = oy * 4 - 2 + ky;
        if ((unsigned)y < 64u) {
#pragma unroll
            for (int kx = 0; kx < 4; kx++) {
                int xx = ox * 4 - 2 + kx;
                if ((unsigned)xx < 64u)
                    acc = fmaf(wp[ky * 4 + kx], ip[y * 64 + xx], acc);
            }
        }
    }
    __shared__ float s1[16], s2[16];
    float v1 = acc, v2 = acc * acc;
#pragma unroll
    for (int o = 16; o > 0; o >>= 1) {
        v1 += __shfl_xor_sync(0xffffffffu, v1, o);
        v2 += __shfl_xor_sync(0xffffffffu, v2, o);
    }
    int w = threadIdx.x >> 5, lane = threadIdx.x & 31;
    if (lane == 0) { s1[w] = v1; s2[w] = v2; }
    __syncthreads();
    if (w == 0) {
        v1 = (lane < 16) ? s1[lane] : 0.f;
        v2 = (lane < 16) ? s2[lane] : 0.f;
#pragma unroll
        for (int o = 8; o > 0; o >>= 1) {
            v1 += __shfl_xor_sync(0xffffffffu, v1, o);
            v2 += __shfl_xor_sync(0xffffffffu, v2, o);
        }
        if (lane == 0) { s1[0] = v1; s2[0] = v2; }
    }
    __syncthreads();
    float mean = s1[0] * (1.f / 512.f);
    float var  = s2[0] * (1.f / 512.f) - mean * mean;
    float val  = (acc - mean) * rsqrtf(var + 1e-5f) * lng[c] + lnb[c];
    __nv_bfloat16 h = __float2bfloat16(val);
    long o = ((long)b * 289 + pos) * 512 + c;
    oh[o] = h;
    ol[o] = __float2bfloat16(val - __bfloat162float(h));
}

// ---------------------------------------------------------------------------
// HMMA GEMM: Out[b][tok][co] = sum_ci W[co][ci] * A[b][tok][ci]
// Tile M=128(co) x N=128(tok), K chunks of 32, bf16 hi/lo x3 mma passes.
// block 256 (8 warps: 2(M) x 4(N), warp tile 64x32 via m16n8k16).
// SMEM/tile row stride 40 bf16 (80B) -> conflict-free fragment LDS.
// asel: 0=semT 1=kpreT 2=vpreT 3=aoT ; osel: 0=qT 1=kT 2=vT 3=extOut(ch-major)
// ---------------------------------------------------------------------------
#define GST 40960          // bytes per stage (4 tiles x 128 x 40 bf16)
#define GSM (2 * GST)      // 81920

__global__ __launch_bounds__(256, 1)
void gemm_mma(int asel, int widx, int osel, float* __restrict__ extOut, int Ntok)
{
    extern __shared__ char sm[];
    const uint32_t smb = smem_u32(sm);
    const int t = threadIdx.x, wid = t >> 5, lane = t & 31;
    const int qr = lane >> 2, qc = lane & 3;
    const int b = blockIdx.z, m0 = blockIdx.y * 128, n0 = blockIdx.x * 128;
    const int wm = wid >> 2, wn = wid & 3;

    const __nv_bfloat16* Ahi = (asel == 0) ? g_semT_hi : (asel == 1) ? g_kpreT_hi
                             : (asel == 2) ? g_vpreT_hi : g_aoT_hi;
    const __nv_bfloat16* Alo = (asel == 0) ? g_semT_lo : (asel == 1) ? g_kpreT_lo
                             : (asel == 2) ? g_vpreT_lo : g_aoT_lo;
    Ahi += (long)b * Ntok * 512;
    Alo += (long)b * Ntok * 512;
    const __nv_bfloat16* Whi = g_whi + (long)widx * 262144;
    const __nv_bfloat16* Wlo = g_wlo + (long)widx * 262144;

    float acc[4][4][4];
#pragma unroll
    for (int i = 0; i < 4; i++)
#pragma unroll
        for (int j = 0; j < 4; j++)
#pragma unroll
            for (int k = 0; k < 4; k++) acc[i][j][k] = 0.f;

    auto load_chunk = [&](int c, int stage) {
        const int k0 = c * 32;
        const uint32_t sb = smb + stage * GST;
#pragma unroll
        for (int u = 0; u < 2; u++) {
            int q = t + 256 * u;
            int row = q >> 2, cq = q & 3;
            uint32_t soff = (uint32_t)(row * 80 + cq * 16);
            long wof = ((long)(m0 + row) << 9) + k0 + cq * 8;
            cpa16(sb + soff,         Whi + wof, 16u);
            cpa16(sb + 10240 + soff, Wlo + wof, 16u);
            int tok = n0 + row;
            uint32_t asz = (tok < Ntok) ? 16u : 0u;
            long aof = ((long)(asz ? tok : 0) << 9) + k0 + cq * 8;
            cpa16(sb + 20480 + soff, Ahi + aof, asz);
            cpa16(sb + 30720 + soff, Alo + aof, asz);
        }
        CPA_COMMIT();
    };

    load_chunk(0, 0);

    for (int c = 0; c < 16; c++) {
        CPA_WAIT0();
        __syncthreads();
        if (c + 1 < 16) load_chunk(c + 1, (c + 1) & 1);

        const uint32_t* SW0 = (const uint32_t*)(sm + (c & 1) * GST);
        const uint32_t* SW1 = SW0 + 2560;   // Wlo
        const uint32_t* SA0 = SW0 + 5120;   // Ahi
        const uint32_t* SA1 = SW0 + 7680;   // Alo
#pragma unroll
        for (int ks = 0; ks < 2; ks++) {
            uint32_t awh[4][4], awl[4][4], bh[4][2], bl[4][2];
#pragma unroll
            for (int mt = 0; mt < 4; mt++) {
                int base = (wm * 64 + mt * 16 + qr) * 20 + qc + ks * 8;
                awh[mt][0] = SW0[base];       awh[mt][1] = SW0[base + 160];
                awh[mt][2] = SW0[base + 4];   awh[mt][3] = SW0[base + 164];
                awl[mt][0] = SW1[base];       awl[mt][1] = SW1[base + 160];
                awl[mt][2] = SW1[base + 4];   awl[mt][3] = SW1[base + 164];
            }
#pragma unroll
            for (int nt = 0; nt < 4; nt++) {
                int bb = (wn * 32 + nt * 8 + qr) * 20 + qc + ks * 8;
                bh[nt][0] = SA0[bb]; bh[nt][1] = SA0[bb + 4];
                bl[nt][0] = SA1[bb]; bl[nt][1] = SA1[bb + 4];
            }
#pragma unroll
            for (int mt = 0; mt < 4; mt++)
#pragma unroll
                for (int nt = 0; nt < 4; nt++) {
                    mma_bf16(acc[mt][nt], awh[mt], bh[nt]);
                    mma_bf16(acc[mt][nt], awh[mt], bl[nt]);
                    mma_bf16(acc[mt][nt], awl[mt], bh[nt]);
                }
        }
    }

    // ---- epilogue: stage through SMEM for coalesced stores ----
    __syncthreads();
    float* Osm = (float*)sm;   // [128][132]
#pragma unroll
    for (int mt = 0; mt < 4; mt++) {
        int ml = wm * 64 + mt * 16 + qr;
#pragma unroll
        for (int nt = 0; nt < 4; nt++) {
            int nl = wn * 32 + nt * 8 + qc * 2;
            if (osel < 3) {   // token-major [tok][co]
                Osm[nl * 132 + ml]           = acc[mt][nt][0];
                Osm[(nl + 1) * 132 + ml]     = acc[mt][nt][1];
                Osm[nl * 132 + ml + 8]       = acc[mt][nt][2];
                Osm[(nl + 1) * 132 + ml + 8] = acc[mt][nt][3];
            } else {          // channel-major [co][tok]
                Osm[ml * 132 + nl]           = acc[mt][nt][0];
                Osm[ml * 132 + nl + 1]       = acc[mt][nt][1];
                Osm[(ml + 8) * 132 + nl]     = acc[mt][nt][2];
                Osm[(ml + 8) * 132 + nl + 1] = acc[mt][nt][3];
            }
        }
    }
    __syncthreads();

    if (osel < 3) {
        float* Out = ((osel == 0) ? g_qT : (osel == 1) ? g_kT : g_vT)
                   + (long)b * Ntok * 512;
#pragma unroll 4
        for (int u = 0; u < 64; u++) {
            int idx = t + 256 * u;
            int tl = idx >> 7, co = idx & 127;
            int tok = n0 + tl;
            if (tok < Ntok) Out[((long)tok << 9) + m0 + co] = Osm[tl * 132 + co];
        }
    } else {
#pragma unroll 4
        for (int u = 0; u < 64; u++) {
            int idx = t + 256 * u;
            int cl = idx >> 7, tl = idx & 127;
            extOut[((long)b * 512 + m0 + cl) * 4096 + n0 + tl] = Osm[cl * 132 + tl];
        }
    }
}

// ---------------------------------------------------------------------------
// attention (fp32 SIMT; token-major I/O; bf16 hi/lo epilogue)
// grid (128, 64), block 256
// ---------------------------------------------------------------------------
#define SC_STRIDE 296
#define ATTN_SMEM ((289 * 65 + 289 * 64 + 32 * 65 + 32 * SC_STRIDE) * 4)

__global__ __launch_bounds__(256)
void attn_kernel()
{
    extern __shared__ float smf[];
    float* Ks = smf;                     // [289][65]
    float* Vs = Ks + 289 * 65;           // [289][64]
    float* Qs = Vs + 289 * 64;           // [32][65]
    float* Sc = Qs + 32 * 65;            // [32][296]

    const int bh = blockIdx.y;
    const int b  = bh >> 3, hh = bh & 7;
    const int n0 = blockIdx.x * 32;
    const int t  = threadIdx.x;

    const float* kb = g_kT + ((long)b * 289) * 512 + hh * 64;
    const float* vb = g_vT + ((long)b * 289) * 512 + hh * 64;
    const float* qb = g_qT + ((long)b * 4096 + n0) * 512 + hh * 64;

    for (int idx = t; idx < 289 * 64; idx += 256) {
        int j = idx >> 6, dc = idx & 63;
        Ks[j * 65 + dc] = kb[(long)j * 512 + dc];
        Vs[j * 64 + dc] = vb[(long)j * 512 + dc];
    }
    for (int idx = t; idx < 32 * 64; idx += 256) {
        int dc = idx & 63, nn = idx >> 6;
        Qs[nn * 65 + dc] = qb[(long)nn * 512 + dc];
    }
    __syncthreads();

    const int row = t >> 3, tsub = t & 7;
    float acc[37];
#pragma unroll
    for (int i = 0; i < 37; i++) acc[i] = 0.f;

    for (int dc0 = 0; dc0 < 64; dc0 += 8) {
        float qr[8];
#pragma unroll
        for (int u = 0; u < 8; u++) qr[u] = Qs[row * 65 + dc0 + u];
#pragma unroll
        for (int i = 0; i < 37; i++) {
            int j = tsub + i * 8;
            if (j < NKV) {
                const float* kp = &Ks[j * 65 + dc0];
                float a = acc[i];
#pragma unroll
                for (int u = 0; u < 8; u++) a = fmaf(qr[u], kp[u], a);
                acc[i] = a;
            }
        }
    }

    float mx = -1e30f;
#pragma unroll
    for (int i = 0; i < 37; i++) {
        int j = tsub + i * 8;
        if (j < NKV) mx = fmaxf(mx, acc[i]);
    }
#pragma unroll
    for (int o = 4; o > 0; o >>= 1) mx = fmaxf(mx, __shfl_xor_sync(0xffffffffu, mx, o));
    float sum = 0.f;
#pragma unroll
    for (int i = 0; i < 37; i++) {
        int j = tsub + i * 8;
        if (j < NKV) { float e = __expf(acc[i] - mx); acc[i] = e; sum += e; }
    }
#pragma unroll
    for (int o = 4; o > 0; o >>= 1) sum += __shfl_xor_sync(0xffffffffu, sum, o);
    float inv = 1.f / sum;
#pragma unroll
    for (int i = 0; i < 37; i++) {
        int j = tsub + i * 8;
        if (j < NKV) Sc[row * SC_STRIDE + j] = acc[i] * inv;
    }
    __syncthreads();

    const int dc = t & 63, rg = t >> 6;
    float o[8];
#pragma unroll
    for (int r = 0; r < 8; r++) o[r] = 0.f;
    for (int j = 0; j < NKV; j++) {
        float vv = Vs[j * 64 + dc];
#pragma unroll
        for (int r = 0; r < 8; r++)
            o[r] = fmaf(Sc[(rg * 8 + r) * SC_STRIDE + j], vv, o[r]);
    }
#pragma unroll
    for (int r = 0; r < 8; r++) {
        int n = n0 + rg * 8 + r;
        float v = o[r];
        __nv_bfloat16 h = __float2bfloat16(v);
        long off = ((long)b * 4096 + n) * 512 + hh * 64 + dc;
        g_aoT_hi[off] = h;
        g_aoT_lo[off] = __float2bfloat16(v - __bfloat162float(h));
    }
}

// ---------------------------------------------------------------------------
// launcher
// ---------------------------------------------------------------------------
extern "C" void kernel_launch(void* const* d_in, const int* in_sizes, int n_in,
                              void* d_out, int out_size)
{
    const float* sem  = (const float*)d_in[0];
    const float* spa  = (const float*)d_in[1];
    const float* x    = (const float*)d_in[2];
    const float* wq   = (const float*)d_in[3];
    const float* wdw  = (const float*)d_in[4];
    const float* lng  = (const float*)d_in[5];
    const float* lnb  = (const float*)d_in[6];
    const float* wpw  = (const float*)d_in[7];
    const float* wout = (const float*)d_in[8];
    float* out = (float*)d_out;

    cudaFuncSetAttribute(gemm_mma, cudaFuncAttributeMaxDynamicSharedMemorySize, GSM);
    cudaFuncSetAttribute(attn_kernel, cudaFuncAttributeMaxDynamicSharedMemorySize, ATTN_SMEM);

    // prep
    prep_w<<<3072, 256>>>(wq, wpw, wout);
    transpose_split<<<dim3(128, 16, 8), dim3(32, 8)>>>(sem);
    dwln_kernel<<<dim3(289, 8), 512>>>(spa, wdw, lng, lnb, 0);
    dwln_kernel<<<dim3(289, 8), 512>>>(x,   wdw, lng, lnb, 1);

    // q = (0.125*wq) @ sem -> g_qT (token-major)
    gemm_mma<<<dim3(32, 4, 8), 256, GSM>>>(0, 0, 0, nullptr, HWQ);
    // k = wpw @ kpre, v = wpw @ vpre
    gemm_mma<<<dim3(3, 4, 8), 256, GSM>>>(1, 1, 1, nullptr, NKV);
    gemm_mma<<<dim3(3, 4, 8), 256, GSM>>>(2, 1, 2, nullptr, NKV);
    // attention -> g_aoT hi/lo
    attn_kernel<<<dim3(128, 64), 256, ATTN_SMEM>>>();
    // out = wout @ ao -> d_out (channel-major)
    gemm_mma<<<dim3(32, 4, 8), 256, GSM>>>(3, 2, 3, out, HWQ);
}

// round 6
// speedup vs baseline: 3.8154x; 2.4510x over previous
#include <cuda_runtime.h>
#include <cuda_bf16.h>
#include <cstdint>
#include <math.h>

// ===========================================================================
// S2Attention on GB300 (sm_103 portable mma.sync path)
//   - 1x1 convs: bf16 hi/lo m16n8k16 GEMMs (3 passes -> ~fp32 accuracy)
//   - attention: fully tensorized, scores in registers
// B=8, C=512, H=W=64, HEADS=8, d=64, kv tokens 17x17=289 (pad 296/304)
// ===========================================================================

#define HWQ  4096
#define NKV  289

// ---------------- device scratch ----------------
__device__ __align__(256) __nv_bfloat16 g_semT_hi[8L * 4096 * 512];
__device__ __align__(256) __nv_bfloat16 g_semT_lo[8L * 4096 * 512];
__device__ __align__(256) __nv_bfloat16 g_kpreT_hi[8L * 289 * 512];
__device__ __align__(256) __nv_bfloat16 g_kpreT_lo[8L * 289 * 512];
__device__ __align__(256) __nv_bfloat16 g_vpreT_hi[8L * 289 * 512];
__device__ __align__(256) __nv_bfloat16 g_vpreT_lo[8L * 289 * 512];
__device__ __align__(256) __nv_bfloat16 g_aoT_hi[8L * 4096 * 512];
__device__ __align__(256) __nv_bfloat16 g_aoT_lo[8L * 4096 * 512];
__device__ __align__(256) __nv_bfloat16 g_qT_hi[8L * 4096 * 512];  // [b][tok][512] q*0.125
__device__ __align__(256) __nv_bfloat16 g_qT_lo[8L * 4096 * 512];
__device__ __align__(256) __nv_bfloat16 g_kT_hi[8L * 289 * 512];   // [b][tok][512]
__device__ __align__(256) __nv_bfloat16 g_kT_lo[8L * 289 * 512];
__device__ __align__(256) __nv_bfloat16 g_vC_hi[8L * 512 * 296];   // [b][c][296] pad0
__device__ __align__(256) __nv_bfloat16 g_vC_lo[8L * 512 * 296];
__device__ __align__(256) float g_preK[8L * 289 * 512];            // [b][pos][c]
__device__ __align__(256) float g_preV[8L * 289 * 512];
__device__ __align__(256) __nv_bfloat16 g_whi[3L * 512 * 512];     // 0=wq*0.125,1=wpw,2=wout
__device__ __align__(256) __nv_bfloat16 g_wlo[3L * 512 * 512];

// ---------------- helpers ----------------
__device__ __forceinline__ uint32_t smem_u32(const void* p) {
    uint32_t a;
    asm("{ .reg .u64 t; cvta.to.shared.u64 t, %1; cvt.u32.u64 %0, t; }"
        : "=r"(a) : "l"(p));
    return a;
}
__device__ __forceinline__ void mma_bf16(float* d, const uint32_t* a, const uint32_t* b) {
    asm volatile(
        "mma.sync.aligned.m16n8k16.row.col.f32.bf16.bf16.f32 "
        "{%0,%1,%2,%3}, {%4,%5,%6,%7}, {%8,%9}, {%0,%1,%2,%3};"
        : "+f"(d[0]), "+f"(d[1]), "+f"(d[2]), "+f"(d[3])
        : "r"(a[0]), "r"(a[1]), "r"(a[2]), "r"(a[3]), "r"(b[0]), "r"(b[1]));
}
__device__ __forceinline__ void cpa16(uint32_t dst, const void* src, uint32_t nbytes) {
    asm volatile("cp.async.cg.shared.global [%0], [%1], 16, %2;"
                 :: "r"(dst), "l"(src), "r"(nbytes) : "memory");
}
#define CPA_COMMIT() asm volatile("cp.async.commit_group;" ::: "memory")
#define CPA_WAIT0()  asm volatile("cp.async.wait_group 0;" ::: "memory")

__device__ __forceinline__ uint32_t packbf(float hi, float lo) {
    uint32_t r;
    asm("cvt.rn.bf16x2.f32 %0, %1, %2;" : "=r"(r) : "f"(hi), "f"(lo));
    return r;  // lower half <- lo, upper half <- hi
}

// ---------------------------------------------------------------------------
// prep: weights -> bf16 hi/lo (wq pre-scaled by 0.125)
// ---------------------------------------------------------------------------
__global__ void prep_w(const float* __restrict__ wq, const float* __restrict__ wpw,
                       const float* __restrict__ wout)
{
    int i = blockIdx.x * 256 + threadIdx.x;
    if (i >= 3 * 262144) return;
    int widx = i >> 18, j = i & 262143;
    float v = (widx == 0) ? wq[j] * 0.125f : (widx == 1) ? wpw[j] : wout[j];
    __nv_bfloat16 h = __float2bfloat16(v);
    g_whi[i] = h;
    g_wlo[i] = __float2bfloat16(v - __bfloat162float(h));
}

// ---------------------------------------------------------------------------
// transpose + split: sem [b][c][4096] fp32 -> g_semT hi/lo [b][tok][512]
// ---------------------------------------------------------------------------
__global__ __launch_bounds__(256)
void transpose_split(const float* __restrict__ in)
{
    __shared__ float tile[32][33];
    int b = blockIdx.z, n0 = blockIdx.x * 32, c0 = blockIdx.y * 32;
    int tx = threadIdx.x, ty = threadIdx.y;
#pragma unroll
    for (int k = 0; k < 4; k++) {
        int c = c0 + ty + 8 * k;
        tile[ty + 8 * k][tx] = in[((long)b * 512 + c) * 4096 + n0 + tx];
    }
    __syncthreads();
#pragma unroll
    for (int k = 0; k < 4; k++) {
        int n = n0 + ty + 8 * k;
        float v = tile[tx][ty + 8 * k];
        __nv_bfloat16 h = __float2bfloat16(v);
        long o = ((long)b * 4096 + n) * 512 + c0 + tx;
        g_semT_hi[o] = h;
        g_semT_lo[o] = __float2bfloat16(v - __bfloat162float(h));
    }
}

// ---------------------------------------------------------------------------
// depthwise 4x4 s4 p2 conv, coalesced: one block per (c, b)
// ---------------------------------------------------------------------------
__global__ __launch_bounds__(128)
void dw_kernel(const float* __restrict__ in, const float* __restrict__ wdw, int osel)
{
    __shared__ float plane[4096];
    const int c = blockIdx.x, b = blockIdx.y, t = threadIdx.x;
    float* outp = osel ? g_preV : g_preK;
    const float4* ip = (const float4*)(in + ((long)b * 512 + c) * 4096);
#pragma unroll
    for (int i = t; i < 1024; i += 128) ((float4*)plane)[i] = ip[i];
    float wr[16];
#pragma unroll
    for (int i = 0; i < 16; i++) wr[i] = wdw[c * 16 + i];
    __syncthreads();

    for (int pos = t; pos < 289; pos += 128) {
        int oy = pos / 17, ox = pos - oy * 17;
        float acc = 0.f;
#pragma unroll
        for (int ky = 0; ky < 4; ky++) {
            int y = oy * 4 - 2 + ky;
            if ((unsigned)y < 64u) {
#pragma unroll
                for (int kx = 0; kx < 4; kx++) {
                    int xx = ox * 4 - 2 + kx;
                    if ((unsigned)xx < 64u)
                        acc = fmaf(wr[ky * 4 + kx], plane[y * 64 + xx], acc);
                }
            }
        }
        outp[((long)b * 289 + pos) * 512 + c] = acc;
    }
}

// ---------------------------------------------------------------------------
// channel LayerNorm per token -> token-major bf16 hi/lo. grid (289,8), block 512
// ---------------------------------------------------------------------------
__global__ __launch_bounds__(512)
void ln_kernel(const float* __restrict__ lng, const float* __restrict__ lnb, int osel)
{
    const float* inp = osel ? g_preV : g_preK;
    __nv_bfloat16* oh = osel ? g_vpreT_hi : g_kpreT_hi;
    __nv_bfloat16* ol = osel ? g_vpreT_lo : g_kpreT_lo;
    const int pos = blockIdx.x, b = blockIdx.y, c = threadIdx.x;
    float acc = inp[((long)b * 289 + pos) * 512 + c];

    __shared__ float s1[16], s2[16];
    float v1 = acc, v2 = acc * acc;
#pragma unroll
    for (int o = 16; o > 0; o >>= 1) {
        v1 += __shfl_xor_sync(0xffffffffu, v1, o);
        v2 += __shfl_xor_sync(0xffffffffu, v2, o);
    }
    int w = threadIdx.x >> 5, lane = threadIdx.x & 31;
    if (lane == 0) { s1[w] = v1; s2[w] = v2; }
    __syncthreads();
    if (w == 0) {
        v1 = (lane < 16) ? s1[lane] : 0.f;
        v2 = (lane < 16) ? s2[lane] : 0.f;
#pragma unroll
        for (int o = 8; o > 0; o >>= 1) {
            v1 += __shfl_xor_sync(0xffffffffu, v1, o);
            v2 += __shfl_xor_sync(0xffffffffu, v2, o);
        }
        if (lane == 0) { s1[0] = v1; s2[0] = v2; }
    }
    __syncthreads();
    float mean = s1[0] * (1.f / 512.f);
    float var  = s2[0] * (1.f / 512.f) - mean * mean;
    float val  = (acc - mean) * rsqrtf(var + 1e-5f) * lng[c] + lnb[c];
    __nv_bfloat16 h = __float2bfloat16(val);
    long o = ((long)b * 289 + pos) * 512 + c;
    oh[o] = h;
    ol[o] = __float2bfloat16(val - __bfloat162float(h));
}

// ---------------------------------------------------------------------------
// HMMA GEMM: Out[b][tok][co] = sum_ci W[co][ci] * A[b][tok][ci]
// ---------------------------------------------------------------------------
#define GST 40960
#define GSM (2 * GST)

__global__ __launch_bounds__(256, 1)
void gemm_mma(int asel, int widx, int osel, float* __restrict__ extOut, int Ntok)
{
    extern __shared__ char sm[];
    const uint32_t smb = smem_u32(sm);
    const int t = threadIdx.x, wid = t >> 5, lane = t & 31;
    const int qr = lane >> 2, qc = lane & 3;
    const int b = blockIdx.z, m0 = blockIdx.y * 128, n0 = blockIdx.x * 128;
    const int wm = wid >> 2, wn = wid & 3;

    const __nv_bfloat16* Ahi = (asel == 0) ? g_semT_hi : (asel == 1) ? g_kpreT_hi
                             : (asel == 2) ? g_vpreT_hi : g_aoT_hi;
    const __nv_bfloat16* Alo = (asel == 0) ? g_semT_lo : (asel == 1) ? g_kpreT_lo
                             : (asel == 2) ? g_vpreT_lo : g_aoT_lo;
    Ahi += (long)b * Ntok * 512;
    Alo += (long)b * Ntok * 512;
    const __nv_bfloat16* Whi = g_whi + (long)widx * 262144;
    const __nv_bfloat16* Wlo = g_wlo + (long)widx * 262144;

    float acc[4][4][4];
#pragma unroll
    for (int i = 0; i < 4; i++)
#pragma unroll
        for (int j = 0; j < 4; j++)
#pragma unroll
            for (int k = 0; k < 4; k++) acc[i][j][k] = 0.f;

    auto load_chunk = [&](int c, int stage) {
        const int k0 = c * 32;
        const uint32_t sb = smb + stage * GST;
#pragma unroll
        for (int u = 0; u < 2; u++) {
            int q = t + 256 * u;
            int row = q >> 2, cq = q & 3;
            uint32_t soff = (uint32_t)(row * 80 + cq * 16);
            long wof = ((long)(m0 + row) << 9) + k0 + cq * 8;
            cpa16(sb + soff,         Whi + wof, 16u);
            cpa16(sb + 10240 + soff, Wlo + wof, 16u);
            int tok = n0 + row;
            uint32_t asz = (tok < Ntok) ? 16u : 0u;
            long aof = ((long)(asz ? tok : 0) << 9) + k0 + cq * 8;
            cpa16(sb + 20480 + soff, Ahi + aof, asz);
            cpa16(sb + 30720 + soff, Alo + aof, asz);
        }
        CPA_COMMIT();
    };

    load_chunk(0, 0);

    for (int c = 0; c < 16; c++) {
        CPA_WAIT0();
        __syncthreads();
        if (c + 1 < 16) load_chunk(c + 1, (c + 1) & 1);

        const uint32_t* SW0 = (const uint32_t*)(sm + (c & 1) * GST);
        const uint32_t* SW1 = SW0 + 2560;
        const uint32_t* SA0 = SW0 + 5120;
        const uint32_t* SA1 = SW0 + 7680;
#pragma unroll
        for (int ks = 0; ks < 2; ks++) {
            uint32_t awh[4][4], awl[4][4], bh[4][2], bl[4][2];
#pragma unroll
            for (int mt = 0; mt < 4; mt++) {
                int base = (wm * 64 + mt * 16 + qr) * 20 + qc + ks * 8;
                awh[mt][0] = SW0[base];       awh[mt][1] = SW0[base + 160];
                awh[mt][2] = SW0[base + 4];   awh[mt][3] = SW0[base + 164];
                awl[mt][0] = SW1[base];       awl[mt][1] = SW1[base + 160];
                awl[mt][2] = SW1[base + 4];   awl[mt][3] = SW1[base + 164];
            }
#pragma unroll
            for (int nt = 0; nt < 4; nt++) {
                int bb = (wn * 32 + nt * 8 + qr) * 20 + qc + ks * 8;
                bh[nt][0] = SA0[bb]; bh[nt][1] = SA0[bb + 4];
                bl[nt][0] = SA1[bb]; bl[nt][1] = SA1[bb + 4];
            }
#pragma unroll
            for (int mt = 0; mt < 4; mt++)
#pragma unroll
                for (int nt = 0; nt < 4; nt++) {
                    mma_bf16(acc[mt][nt], awh[mt], bh[nt]);
                    mma_bf16(acc[mt][nt], awh[mt], bl[nt]);
                    mma_bf16(acc[mt][nt], awl[mt], bh[nt]);
                }
        }
    }

    // ---- epilogue ----
    __syncthreads();
    float* Osm = (float*)sm;   // [128][132]
    const bool tokmajor = (osel < 2);
#pragma unroll
    for (int mt = 0; mt < 4; mt++) {
        int ml = wm * 64 + mt * 16 + qr;
#pragma unroll
        for (int nt = 0; nt < 4; nt++) {
            int nl = wn * 32 + nt * 8 + qc * 2;
            if (tokmajor) {
                Osm[nl * 132 + ml]           = acc[mt][nt][0];
                Osm[(nl + 1) * 132 + ml]     = acc[mt][nt][1];
                Osm[nl * 132 + ml + 8]       = acc[mt][nt][2];
                Osm[(nl + 1) * 132 + ml + 8] = acc[mt][nt][3];
            } else {
                Osm[ml * 132 + nl]           = acc[mt][nt][0];
                Osm[ml * 132 + nl + 1]       = acc[mt][nt][1];
                Osm[(ml + 8) * 132 + nl]     = acc[mt][nt][2];
                Osm[(ml + 8) * 132 + nl + 1] = acc[mt][nt][3];
            }
        }
    }
    __syncthreads();

    if (osel <= 1) {
        __nv_bfloat16* Oh = (osel == 0) ? g_qT_hi : g_kT_hi;
        __nv_bfloat16* Ol = (osel == 0) ? g_qT_lo : g_kT_lo;
#pragma unroll 4
        for (int u = 0; u < 64; u++) {
            int idx = t + 256 * u;
            int tl = idx >> 7, co = idx & 127;
            int tok = n0 + tl;
            if (tok < Ntok) {
                float v = Osm[tl * 132 + co];
                __nv_bfloat16 h = __float2bfloat16(v);
                long off = ((long)b * Ntok + tok) * 512 + m0 + co;
                Oh[off] = h;
                Ol[off] = __float2bfloat16(v - __bfloat162float(h));
            }
        }
    } else if (osel == 2) {
#pragma unroll 4
        for (int u = 0; u < 64; u++) {
            int idx = t + 256 * u;
            int cl = idx >> 7, tl = idx & 127;
            int tok = n0 + tl;
            if (tok < Ntok) {
                float v = Osm[cl * 132 + tl];
                __nv_bfloat16 h = __float2bfloat16(v);
                long off = ((long)b * 512 + m0 + cl) * 296 + tok;
                g_vC_hi[off] = h;
                g_vC_lo[off] = __float2bfloat16(v - __bfloat162float(h));
            }
        }
    } else {
#pragma unroll 4
        for (int u = 0; u < 64; u++) {
            int idx = t + 256 * u;
            int cl = idx >> 7, tl = idx & 127;
            extOut[((long)b * 512 + m0 + cl) * 4096 + n0 + tl] = Osm[cl * 132 + tl];
        }
    }
}

// ---------------------------------------------------------------------------
// Tensorized attention. Block = (bh, 128-token q-tile). 8 warps x 16 q-rows.
// Q/K rows: 64 bf16 data, stride 36 words (72 bf16). V rows: stride 156 words.
// SQ hi[0] lo[4608] (128x36); SK hi[9216] lo[19872] (296x36);
// SV hi[30528] lo[40512] (64x156). Total 50496 words = 201984 B.
// ---------------------------------------------------------------------------
#define SQL_  4608
#define SKH_  9216
#define SKL_  19872
#define SVH_  30528
#define SVL_  40512
#define ATTN_SMEM (50496 * 4)

__global__ __launch_bounds__(256, 1)
void attn_kernel()
{
    extern __shared__ uint32_t smw[];
    uint4* s4 = (uint4*)smw;
    const int bh = blockIdx.y, b = bh >> 3, hh = bh & 7;
    const int n0 = blockIdx.x * 128;
    const int t = threadIdx.x, w = t >> 5, lane = t & 31;
    const int qr = lane >> 2, qc = lane & 3;

    // ---- loads (row = 8 uint4 data, stride 9 uint4 for Q/K) ----
    {
        const long qoff = ((long)(b * 4096 + n0)) * 512 + hh * 64;
        const uint4* qh4 = (const uint4*)(g_qT_hi + qoff);
        const uint4* ql4 = (const uint4*)(g_qT_lo + qoff);
        for (int idx = t; idx < 1024; idx += 256) {
            int row = idx >> 3, j = idx & 7;
            s4[row * 9 + j]            = qh4[row * 64 + j];
            s4[SQL_ / 4 + row * 9 + j] = ql4[row * 64 + j];
        }
        const long koff = ((long)b * 289) * 512 + hh * 64;
        const uint4* kh4 = (const uint4*)(g_kT_hi + koff);
        const uint4* kl4 = (const uint4*)(g_kT_lo + koff);
        for (int idx = t; idx < 2312; idx += 256) {
            int row = idx >> 3, j = idx & 7;
            s4[SKH_ / 4 + row * 9 + j] = kh4[row * 64 + j];
            s4[SKL_ / 4 + row * 9 + j] = kl4[row * 64 + j];
        }
        for (int idx = t; idx < 252; idx += 256) {   // zero K rows 289..295
            smw[SKH_ + 10404 + idx] = 0;
            smw[SKL_ + 10404 + idx] = 0;
        }
        const long voff = ((long)(b * 512 + hh * 64)) * 296;
        const uint4* vh4 = (const uint4*)(g_vC_hi + voff);
        const uint4* vl4 = (const uint4*)(g_vC_lo + voff);
        for (int idx = t; idx < 2368; idx += 256) {
            int row = idx / 37, j = idx - row * 37;
            s4[SVH_ / 4 + row * 39 + j] = vh4[row * 37 + j];
            s4[SVL_ / 4 + row * 39 + j] = vl4[row * 37 + j];
        }
        for (int idx = t; idx < 512; idx += 256) {   // zero V cols 296..311
            int row = idx >> 3, ww = idx & 7;
            smw[SVH_ + row * 156 + 148 + ww] = 0;
            smw[SVL_ + row * 156 + 148 + ww] = 0;
        }
    }
    __syncthreads();

    // ---- QK^T: scores in registers ----
    float s[37][4];
#pragma unroll
    for (int nt = 0; nt < 37; nt++)
#pragma unroll
        for (int r = 0; r < 4; r++) s[nt][r] = 0.f;

    const int qrowbase = (w * 16 + qr) * 36 + qc;
#pragma unroll
    for (int kk = 0; kk < 4; kk++) {
        int qb = qrowbase + kk * 8;
        uint32_t ah[4] = { smw[qb], smw[qb + 288], smw[qb + 4], smw[qb + 292] };
        uint32_t al[4] = { smw[SQL_ + qb], smw[SQL_ + qb + 288],
                           smw[SQL_ + qb + 4], smw[SQL_ + qb + 292] };
        int kbase = SKH_ + qr * 36 + kk * 8 + qc;
#pragma unroll
        for (int nt = 0; nt < 37; nt++) {
            int kb = kbase + nt * 288;
            uint32_t bh[2] = { smw[kb], smw[kb + 4] };
            uint32_t bl[2] = { smw[kb + (SKL_ - SKH_)], smw[kb + (SKL_ - SKH_) + 4] };
            mma_bf16(s[nt], ah, bh);
            mma_bf16(s[nt], ah, bl);
            mma_bf16(s[nt], al, bh);
        }
    }

    // ---- softmax (rows qr -> regs 0,1 ; qr+8 -> regs 2,3) ----
    float mx0 = -1e30f, mx1 = -1e30f;
#pragma unroll
    for (int nt = 0; nt < 36; nt++) {
        mx0 = fmaxf(mx0, fmaxf(s[nt][0], s[nt][1]));
        mx1 = fmaxf(mx1, fmaxf(s[nt][2], s[nt][3]));
    }
    if (qc == 0) { mx0 = fmaxf(mx0, s[36][0]); mx1 = fmaxf(mx1, s[36][2]); }
    mx0 = fmaxf(mx0, __shfl_xor_sync(0xffffffffu, mx0, 1));
    mx0 = fmaxf(mx0, __shfl_xor_sync(0xffffffffu, mx0, 2));
    mx1 = fmaxf(mx1, __shfl_xor_sync(0xffffffffu, mx1, 1));
    mx1 = fmaxf(mx1, __shfl_xor_sync(0xffffffffu, mx1, 2));

    float sum0 = 0.f, sum1 = 0.f;
#pragma unroll
    for (int nt = 0; nt < 36; nt++) {
        float e0 = __expf(s[nt][0] - mx0), e1 = __expf(s[nt][1] - mx0);
        float e2 = __expf(s[nt][2] - mx1), e3 = __expf(s[nt][3] - mx1);
        s[nt][0] = e0; s[nt][1] = e1; s[nt][2] = e2; s[nt][3] = e3;
        sum0 += e0 + e1; sum1 += e2 + e3;
    }
    {
        float e0 = (qc == 0) ? __expf(s[36][0] - mx0) : 0.f;
        float e2 = (qc == 0) ? __expf(s[36][2] - mx1) : 0.f;
        s[36][0] = e0; s[36][1] = 0.f; s[36][2] = e2; s[36][3] = 0.f;
        sum0 += e0; sum1 += e2;
    }
    sum0 += __shfl_xor_sync(0xffffffffu, sum0, 1);
    sum0 += __shfl_xor_sync(0xffffffffu, sum0, 2);
    sum1 += __shfl_xor_sync(0xffffffffu, sum1, 1);
    sum1 += __shfl_xor_sync(0xffffffffu, sum1, 2);
    float inv0 = 1.f / sum0, inv1 = 1.f / sum1;

    // ---- P -> bf16 hi/lo packed fragments ----
    uint32_t ph[38][2], pl[38][2];
#pragma unroll
    for (int nt = 0; nt < 37; nt++) {
        float p0 = s[nt][0] * inv0, p1 = s[nt][1] * inv0;
        float p2 = s[nt][2] * inv1, p3 = s[nt][3] * inv1;
        uint32_t u0 = packbf(p1, p0);
        uint32_t u1 = packbf(p3, p2);
        ph[nt][0] = u0; ph[nt][1] = u1;
        float h0 = __uint_as_float(u0 << 16), h1 = __uint_as_float(u0 & 0xFFFF0000u);
        float h2 = __uint_as_float(u1 << 16), h3 = __uint_as_float(u1 & 0xFFFF0000u);
        pl[nt][0] = packbf(p1 - h1, p0 - h0);
        pl[nt][1] = packbf(p3 - h3, p2 - h2);
    }
    ph[37][0] = ph[37][1] = pl[37][0] = pl[37][1] = 0u;

    // ---- AV ----
    float o[8][4];
#pragma unroll
    for (int nt = 0; nt < 8; nt++)
#pragma unroll
        for (int r = 0; r < 4; r++) o[nt][r] = 0.f;

#pragma unroll
    for (int kc = 0; kc < 19; kc++) {
        uint32_t ah[4] = { ph[2 * kc][0], ph[2 * kc][1],
                           ph[2 * kc + 1][0], ph[2 * kc + 1][1] };
        uint32_t al[4] = { pl[2 * kc][0], pl[2 * kc][1],
                           pl[2 * kc + 1][0], pl[2 * kc + 1][1] };
        int vb0 = SVH_ + qr * 156 + kc * 8 + qc;
#pragma unroll
        for (int nt = 0; nt < 8; nt++) {
            int vb = vb0 + nt * 1248;
            uint32_t bh[2] = { smw[vb], smw[vb + 4] };
            uint32_t bl[2] = { smw[vb + (SVL_ - SVH_)], smw[vb + (SVL_ - SVH_) + 4] };
            mma_bf16(o[nt], ah, bh);
            mma_bf16(o[nt], ah, bl);
            mma_bf16(o[nt], al, bh);
        }
    }

    // ---- stage + store (token-major bf16 hi/lo) ----
    __syncthreads();
    float* Osm = (float*)smw;   // [128][68]
#pragma unroll
    for (int nt = 0; nt < 8; nt++) {
        int col = nt * 8 + qc * 2;
        int r0 = (w * 16 + qr) * 68;
        Osm[r0 + col]              = o[nt][0];
        Osm[r0 + col + 1]          = o[nt][1];
        Osm[r0 + 8 * 68 + col]     = o[nt][2];
        Osm[r0 + 8 * 68 + col + 1] = o[nt][3];
    }
    __syncthreads();
    for (int idx = t; idx < 8192; idx += 256) {
        int tok = idx >> 6, dc = idx & 63;
        float v = Osm[tok * 68 + dc];
        __nv_bfloat16 h = __float2bfloat16(v);
        long off = ((long)(b * 4096 + n0 + tok)) * 512 + hh * 64 + dc;
        g_aoT_hi[off] = h;
        g_aoT_lo[off] = __float2bfloat16(v - __bfloat162float(h));
    }
}

// ---------------------------------------------------------------------------
// launcher
// ---------------------------------------------------------------------------
extern "C" void kernel_launch(void* const* d_in, const int* in_sizes, int n_in,
                              void* d_out, int out_size)
{
    const float* sem  = (const float*)d_in[0];
    const float* spa  = (const float*)d_in[1];
    const float* x    = (const float*)d_in[2];
    const float* wq   = (const float*)d_in[3];
    const float* wdw  = (const float*)d_in[4];
    const float* lng  = (const float*)d_in[5];
    const float* lnb  = (const float*)d_in[6];
    const float* wpw  = (const float*)d_in[7];
    const float* wout = (const float*)d_in[8];
    float* out = (float*)d_out;

    cudaFuncSetAttribute(gemm_mma, cudaFuncAttributeMaxDynamicSharedMemorySize, GSM);
    cudaFuncSetAttribute(attn_kernel, cudaFuncAttributeMaxDynamicSharedMemorySize, ATTN_SMEM);

    prep_w<<<3072, 256>>>(wq, wpw, wout);
    transpose_split<<<dim3(128, 16, 8), dim3(32, 8)>>>(sem);
    dw_kernel<<<dim3(512, 8), 128>>>(spa, wdw, 0);
    dw_kernel<<<dim3(512, 8), 128>>>(x,   wdw, 1);
    ln_kernel<<<dim3(289, 8), 512>>>(lng, lnb, 0);
    ln_kernel<<<dim3(289, 8), 512>>>(lng, lnb, 1);

    gemm_mma<<<dim3(32, 4, 8), 256, GSM>>>(0, 0, 0, nullptr, HWQ);
    gemm_mma<<<dim3(3, 4, 8), 256, GSM>>>(1, 1, 1, nullptr, NKV);
    gemm_mma<<<dim3(3, 4, 8), 256, GSM>>>(2, 1, 2, nullptr, NKV);
    attn_kernel<<<dim3(32, 64), 256, ATTN_SMEM>>>();
    gemm_mma<<<dim3(32, 4, 8), 256, GSM>>>(3, 2, 3, out, HWQ);
}

// round 8
// speedup vs baseline: 5.3464x; 1.4013x over previous
#include <cuda_runtime.h>
#include <cuda_fp16.h>
#include <cstdint>
#include <math.h>

// ===========================================================================
// S2Attention on GB300 (sm_103 portable mma.sync path, fp16 numerics)
//   - 1x1 convs: W in fp16 hi/lo (2 MMA passes), activations single fp16
//   - attention: single-pass fp16 HMMA (errors enter softmax absolutely)
// B=8, C=512, H=W=64, HEADS=8, d=64, kv tokens 17x17=289 (pad 296)
// ===========================================================================

#define HWQ  4096
#define NKV  289

// ---------------- device scratch ----------------
__device__ __align__(256) __half g_semT [8L * 4096 * 512];  // [b][tok][512]
__device__ __align__(256) __half g_kpreT[8L * 289 * 512];
__device__ __align__(256) __half g_vpreT[8L * 289 * 512];
__device__ __align__(256) __half g_aoT  [8L * 4096 * 512];
__device__ __align__(256) __half g_qT   [8L * 4096 * 512];  // q*0.125
__device__ __align__(256) __half g_kT   [8L * 289 * 512];
__device__ __align__(256) __half g_vC   [8L * 512 * 296];   // [b][c][296] pad0
__device__ __align__(256) float  g_preK [8L * 289 * 512];   // [b][pos][c]
__device__ __align__(256) float  g_preV [8L * 289 * 512];
__device__ __align__(256) __half g_whi  [3L * 512 * 512];   // 0=wq*0.125,1=wpw,2=wout
__device__ __align__(256) __half g_wlo  [3L * 512 * 512];

// ---------------- helpers ----------------
__device__ __forceinline__ uint32_t smem_u32(const void* p) {
    uint32_t a;
    asm("{ .reg .u64 t; cvta.to.shared.u64 t, %1; cvt.u32.u64 %0, t; }"
        : "=r"(a) : "l"(p));
    return a;
}
__device__ __forceinline__ void mma_f16(float* d, const uint32_t* a, const uint32_t* b) {
    asm volatile(
        "mma.sync.aligned.m16n8k16.row.col.f32.f16.f16.f32 "
        "{%0,%1,%2,%3}, {%4,%5,%6,%7}, {%8,%9}, {%0,%1,%2,%3};"
        : "+f"(d[0]), "+f"(d[1]), "+f"(d[2]), "+f"(d[3])
        : "r"(a[0]), "r"(a[1]), "r"(a[2]), "r"(a[3]), "r"(b[0]), "r"(b[1]));
}
__device__ __forceinline__ void cpa16(uint32_t dst, const void* src, uint32_t nbytes) {
    asm volatile("cp.async.cg.shared.global [%0], [%1], 16, %2;"
                 :: "r"(dst), "l"(src), "r"(nbytes) : "memory");
}
#define CPA_COMMIT() asm volatile("cp.async.commit_group;" ::: "memory")
#define CPA_WAIT0()  asm volatile("cp.async.wait_group 0;" ::: "memory")

__device__ __forceinline__ uint32_t packh(float hi, float lo) {
    uint32_t r;
    asm("cvt.rn.f16x2.f32 %0, %1, %2;" : "=r"(r) : "f"(hi), "f"(lo));
    return r;  // lower half <- lo, upper half <- hi
}

// ---------------------------------------------------------------------------
// prep: weights -> fp16 hi/lo (wq pre-scaled by 0.125)
// ---------------------------------------------------------------------------
__global__ void prep_w(const float* __restrict__ wq, const float* __restrict__ wpw,
                       const float* __restrict__ wout)
{
    int i = blockIdx.x * 256 + threadIdx.x;
    if (i >= 3 * 262144) return;
    int widx = i >> 18, j = i & 262143;
    float v = (widx == 0) ? wq[j] * 0.125f : (widx == 1) ? wpw[j] : wout[j];
    __half h = __float2half_rn(v);
    g_whi[i] = h;
    g_wlo[i] = __float2half_rn(v - __half2float(h));
}

// ---------------------------------------------------------------------------
// transpose: sem [b][c][4096] fp32 -> g_semT fp16 [b][tok][512]
// ---------------------------------------------------------------------------
__global__ __launch_bounds__(256)
void transpose_split(const float* __restrict__ in)
{
    __shared__ float tile[32][33];
    int b = blockIdx.z, n0 = blockIdx.x * 32, c0 = blockIdx.y * 32;
    int tx = threadIdx.x, ty = threadIdx.y;
#pragma unroll
    for (int k = 0; k < 4; k++) {
        int c = c0 + ty + 8 * k;
        tile[ty + 8 * k][tx] = in[((long)b * 512 + c) * 4096 + n0 + tx];
    }
    __syncthreads();
#pragma unroll
    for (int k = 0; k < 4; k++) {
        int n = n0 + ty + 8 * k;
        g_semT[((long)b * 4096 + n) * 512 + c0 + tx] =
            __float2half_rn(tile[tx][ty + 8 * k]);
    }
}

// ---------------------------------------------------------------------------
// depthwise 4x4 s4 p2 conv, coalesced: one block per (c, b)
// ---------------------------------------------------------------------------
__global__ __launch_bounds__(128)
void dw_kernel(const float* __restrict__ in, const float* __restrict__ wdw, int osel)
{
    __shared__ float plane[4096];
    const int c = blockIdx.x, b = blockIdx.y, t = threadIdx.x;
    float* outp = osel ? g_preV : g_preK;
    const float4* ip = (const float4*)(in + ((long)b * 512 + c) * 4096);
#pragma unroll
    for (int i = t; i < 1024; i += 128) ((float4*)plane)[i] = ip[i];
    float wr[16];
#pragma unroll
    for (int i = 0; i < 16; i++) wr[i] = wdw[c * 16 + i];
    __syncthreads();

    for (int pos = t; pos < 289; pos += 128) {
        int oy = pos / 17, ox = pos - oy * 17;
        float acc = 0.f;
#pragma unroll
        for (int ky = 0; ky < 4; ky++) {
            int y = oy * 4 - 2 + ky;
            if ((unsigned)y < 64u) {
#pragma unroll
                for (int kx = 0; kx < 4; kx++) {
                    int xx = ox * 4 - 2 + kx;
                    if ((unsigned)xx < 64u)
                        acc = fmaf(wr[ky * 4 + kx], plane[y * 64 + xx], acc);
                }
            }
        }
        outp[((long)b * 289 + pos) * 512 + c] = acc;
    }
}

// ---------------------------------------------------------------------------
// channel LayerNorm per token -> token-major fp16. grid (289,8), block 512
// ---------------------------------------------------------------------------
__global__ __launch_bounds__(512)
void ln_kernel(const float* __restrict__ lng, const float* __restrict__ lnb, int osel)
{
    const float* inp = osel ? g_preV : g_preK;
    __half* oh = osel ? g_vpreT : g_kpreT;
    const int pos = blockIdx.x, b = blockIdx.y, c = threadIdx.x;
    float acc = inp[((long)b * 289 + pos) * 512 + c];

    __shared__ float s1[16], s2[16];
    float v1 = acc, v2 = acc * acc;
#pragma unroll
    for (int o = 16; o > 0; o >>= 1) {
        v1 += __shfl_xor_sync(0xffffffffu, v1, o);
        v2 += __shfl_xor_sync(0xffffffffu, v2, o);
    }
    int w = threadIdx.x >> 5, lane = threadIdx.x & 31;
    if (lane == 0) { s1[w] = v1; s2[w] = v2; }
    __syncthreads();
    if (w == 0) {
        v1 = (lane < 16) ? s1[lane] : 0.f;
        v2 = (lane < 16) ? s2[lane] : 0.f;
#pragma unroll
        for (int o = 8; o > 0; o >>= 1) {
            v1 += __shfl_xor_sync(0xffffffffu, v1, o);
            v2 += __shfl_xor_sync(0xffffffffu, v2, o);
        }
        if (lane == 0) { s1[0] = v1; s2[0] = v2; }
    }
    __syncthreads();
    float mean = s1[0] * (1.f / 512.f);
    float var  = s2[0] * (1.f / 512.f) - mean * mean;
    float val  = (acc - mean) * rsqrtf(var + 1e-5f) * lng[c] + lnb[c];
    oh[((long)b * 289 + pos) * 512 + c] = __float2half_rn(val);
}

// ---------------------------------------------------------------------------
// HMMA GEMM: Out[b][tok][co] = sum_ci W[co][ci] * A[b][tok][ci]
// W fp16 hi/lo (2 passes), A single fp16. K-chunks of 32, double-buffered.
// Stages use bytes [0, 61440); fp32 epilogue staging needs 67584 B -> GSM.
// ---------------------------------------------------------------------------
#define GST 30720          // 3 tiles x 128 rows x 80 B
#define GSM 67584          // max(2*GST, 128*132*4) -- epilogue staging!

__global__ __launch_bounds__(256, 1)
void gemm_mma(int asel, int widx, int osel, float* __restrict__ extOut, int Ntok)
{
    extern __shared__ char sm[];
    const uint32_t smb = smem_u32(sm);
    const int t = threadIdx.x, wid = t >> 5, lane = t & 31;
    const int qr = lane >> 2, qc = lane & 3;
    const int b = blockIdx.z, m0 = blockIdx.y * 128, n0 = blockIdx.x * 128;
    const int wm = wid >> 2, wn = wid & 3;

    const __half* A = (asel == 0) ? g_semT : (asel == 1) ? g_kpreT
                    : (asel == 2) ? g_vpreT : g_aoT;
    A += (long)b * Ntok * 512;
    const __half* Whi = g_whi + (long)widx * 262144;
    const __half* Wlo = g_wlo + (long)widx * 262144;

    float acc[4][4][4];
#pragma unroll
    for (int i = 0; i < 4; i++)
#pragma unroll
        for (int j = 0; j < 4; j++)
#pragma unroll
            for (int k = 0; k < 4; k++) acc[i][j][k] = 0.f;

    auto load_chunk = [&](int c, int stage) {
        const int k0 = c * 32;
        const uint32_t sb = smb + stage * GST;
#pragma unroll
        for (int u = 0; u < 2; u++) {
            int q = t + 256 * u;
            int row = q >> 2, cq = q & 3;
            uint32_t soff = (uint32_t)(row * 80 + cq * 16);
            long wof = ((long)(m0 + row) << 9) + k0 + cq * 8;
            cpa16(sb + soff,         Whi + wof, 16u);
            cpa16(sb + 10240 + soff, Wlo + wof, 16u);
            int tok = n0 + row;
            uint32_t asz = (tok < Ntok) ? 16u : 0u;
            long aof = ((long)(asz ? tok : 0) << 9) + k0 + cq * 8;
            cpa16(sb + 20480 + soff, A + aof, asz);
        }
        CPA_COMMIT();
    };

    load_chunk(0, 0);

    for (int c = 0; c < 16; c++) {
        CPA_WAIT0();
        __syncthreads();
        if (c + 1 < 16) load_chunk(c + 1, (c + 1) & 1);

        const uint32_t* SW0 = (const uint32_t*)(sm + (c & 1) * GST);
        const uint32_t* SW1 = SW0 + 2560;
        const uint32_t* SA  = SW0 + 5120;
#pragma unroll
        for (int ks = 0; ks < 2; ks++) {
            uint32_t awh[4][4], awl[4][4], bb[4][2];
#pragma unroll
            for (int mt = 0; mt < 4; mt++) {
                int base = (wm * 64 + mt * 16 + qr) * 20 + qc + ks * 8;
                awh[mt][0] = SW0[base];       awh[mt][1] = SW0[base + 160];
                awh[mt][2] = SW0[base + 4];   awh[mt][3] = SW0[base + 164];
                awl[mt][0] = SW1[base];       awl[mt][1] = SW1[base + 160];
                awl[mt][2] = SW1[base + 4];   awl[mt][3] = SW1[base + 164];
            }
#pragma unroll
            for (int nt = 0; nt < 4; nt++) {
                int bo = (wn * 32 + nt * 8 + qr) * 20 + qc + ks * 8;
                bb[nt][0] = SA[bo]; bb[nt][1] = SA[bo + 4];
            }
#pragma unroll
            for (int mt = 0; mt < 4; mt++)
#pragma unroll
                for (int nt = 0; nt < 4; nt++) {
                    mma_f16(acc[mt][nt], awh[mt], bb[nt]);
                    mma_f16(acc[mt][nt], awl[mt], bb[nt]);
                }
        }
    }

    // ---- epilogue ----
    __syncthreads();
    float* Osm = (float*)sm;   // [128][132] = 67584 B (fits GSM)
    const bool tokmajor = (osel < 2);
#pragma unroll
    for (int mt = 0; mt < 4; mt++) {
        int ml = wm * 64 + mt * 16 + qr;
#pragma unroll
        for (int nt = 0; nt < 4; nt++) {
            int nl = wn * 32 + nt * 8 + qc * 2;
            if (tokmajor) {
                Osm[nl * 132 + ml]           = acc[mt][nt][0];
                Osm[(nl + 1) * 132 + ml]     = acc[mt][nt][1];
                Osm[nl * 132 + ml + 8]       = acc[mt][nt][2];
                Osm[(nl + 1) * 132 + ml + 8] = acc[mt][nt][3];
            } else {
                Osm[ml * 132 + nl]           = acc[mt][nt][0];
                Osm[ml * 132 + nl + 1]       = acc[mt][nt][1];
                Osm[(ml + 8) * 132 + nl]     = acc[mt][nt][2];
                Osm[(ml + 8) * 132 + nl + 1] = acc[mt][nt][3];
            }
        }
    }
    __syncthreads();

    if (osel <= 1) {
        __half* Oh = (osel == 0) ? g_qT : g_kT;
#pragma unroll 4
        for (int u = 0; u < 64; u++) {
            int idx = t + 256 * u;
            int tl = idx >> 7, co = idx & 127;
            int tok = n0 + tl;
            if (tok < Ntok)
                Oh[((long)b * Ntok + tok) * 512 + m0 + co] =
                    __float2half_rn(Osm[tl * 132 + co]);
        }
    } else if (osel == 2) {
#pragma unroll 4
        for (int u = 0; u < 64; u++) {
            int idx = t + 256 * u;
            int cl = idx >> 7, tl = idx & 127;
            int tok = n0 + tl;
            if (tok < Ntok)
                g_vC[((long)b * 512 + m0 + cl) * 296 + tok] =
                    __float2half_rn(Osm[cl * 132 + tl]);
        }
    } else {
#pragma unroll 4
        for (int u = 0; u < 64; u++) {
            int idx = t + 256 * u;
            int cl = idx >> 7, tl = idx & 127;
            extOut[((long)b * 512 + m0 + cl) * 4096 + n0 + tl] = Osm[cl * 132 + tl];
        }
    }
}

// ---------------------------------------------------------------------------
// Tensorized attention, single-pass fp16. Block = (bh, 128-token q-tile).
// SQ [0] 128x36w; SK [4608] 296x36w; SV [15264] 64x156w. 25248 w = 100992 B.
// ---------------------------------------------------------------------------
#define SK_  4608
#define SV_  15264
#define ATTN_SMEM (25248 * 4)

__global__ __launch_bounds__(256, 1)
void attn_kernel()
{
    extern __shared__ uint32_t smw[];
    uint4* s4 = (uint4*)smw;
    const int bh = blockIdx.y, b = bh >> 3, hh = bh & 7;
    const int n0 = blockIdx.x * 128;
    const int t = threadIdx.x, w = t >> 5, lane = t & 31;
    const int qr = lane >> 2, qc = lane & 3;

    // ---- loads (Q/K rows: 8 uint4 data, stride 9 uint4) ----
    {
        const uint4* q4 = (const uint4*)(g_qT + ((long)(b * 4096 + n0)) * 512 + hh * 64);
        for (int idx = t; idx < 1024; idx += 256) {
            int row = idx >> 3, j = idx & 7;
            s4[row * 9 + j] = q4[row * 64 + j];
        }
        const uint4* k4 = (const uint4*)(g_kT + ((long)b * 289) * 512 + hh * 64);
        for (int idx = t; idx < 2312; idx += 256) {
            int row = idx >> 3, j = idx & 7;
            s4[SK_ / 4 + row * 9 + j] = k4[row * 64 + j];
        }
        for (int idx = t; idx < 252; idx += 256)     // zero K rows 289..295
            smw[SK_ + 10404 + idx] = 0;
        const uint4* v4 = (const uint4*)(g_vC + ((long)(b * 512 + hh * 64)) * 296);
        for (int idx = t; idx < 2368; idx += 256) {
            int row = idx / 37, j = idx - row * 37;
            s4[SV_ / 4 + row * 39 + j] = v4[row * 37 + j];
        }
        for (int idx = t; idx < 512; idx += 256) {   // zero V cols 296..311
            int row = idx >> 3, ww = idx & 7;
            smw[SV_ + row * 156 + 148 + ww] = 0;
        }
    }
    __syncthreads();

    // ---- QK^T (single pass) ----
    float s[37][4];
#pragma unroll
    for (int nt = 0; nt < 37; nt++)
#pragma unroll
        for (int r = 0; r < 4; r++) s[nt][r] = 0.f;

    const int qrowbase = (w * 16 + qr) * 36 + qc;
#pragma unroll
    for (int kk = 0; kk < 4; kk++) {
        int qb = qrowbase + kk * 8;
        uint32_t a[4] = { smw[qb], smw[qb + 288], smw[qb + 4], smw[qb + 292] };
        int kbase = SK_ + qr * 36 + kk * 8 + qc;
#pragma unroll
        for (int nt = 0; nt < 37; nt++) {
            int kb = kbase + nt * 288;
            uint32_t bb[2] = { smw[kb], smw[kb + 4] };
            mma_f16(s[nt], a, bb);
        }
    }

    // ---- softmax ----
    float mx0 = -1e30f, mx1 = -1e30f;
#pragma unroll
    for (int nt = 0; nt < 36; nt++) {
        mx0 = fmaxf(mx0, fmaxf(s[nt][0], s[nt][1]));
        mx1 = fmaxf(mx1, fmaxf(s[nt][2], s[nt][3]));
    }
    if (qc == 0) { mx0 = fmaxf(mx0, s[36][0]); mx1 = fmaxf(mx1, s[36][2]); }
    mx0 = fmaxf(mx0, __shfl_xor_sync(0xffffffffu, mx0, 1));
    mx0 = fmaxf(mx0, __shfl_xor_sync(0xffffffffu, mx0, 2));
    mx1 = fmaxf(mx1, __shfl_xor_sync(0xffffffffu, mx1, 1));
    mx1 = fmaxf(mx1, __shfl_xor_sync(0xffffffffu, mx1, 2));

    float sum0 = 0.f, sum1 = 0.f;
#pragma unroll
    for (int nt = 0; nt < 36; nt++) {
        float e0 = __expf(s[nt][0] - mx0), e1 = __expf(s[nt][1] - mx0);
        float e2 = __expf(s[nt][2] - mx1), e3 = __expf(s[nt][3] - mx1);
        s[nt][0] = e0; s[nt][1] = e1; s[nt][2] = e2; s[nt][3] = e3;
        sum0 += e0 + e1; sum1 += e2 + e3;
    }
    {
        float e0 = (qc == 0) ? __expf(s[36][0] - mx0) : 0.f;
        float e2 = (qc == 0) ? __expf(s[36][2] - mx1) : 0.f;
        s[36][0] = e0; s[36][1] = 0.f; s[36][2] = e2; s[36][3] = 0.f;
        sum0 += e0; sum1 += e2;
    }
    sum0 += __shfl_xor_sync(0xffffffffu, sum0, 1);
    sum0 += __shfl_xor_sync(0xffffffffu, sum0, 2);
    sum1 += __shfl_xor_sync(0xffffffffu, sum1, 1);
    sum1 += __shfl_xor_sync(0xffffffffu, sum1, 2);
    float inv0 = 1.f / sum0, inv1 = 1.f / sum1;

    // ---- P -> fp16 packed fragments ----
    uint32_t ph[38][2];
#pragma unroll
    for (int nt = 0; nt < 37; nt++) {
        ph[nt][0] = packh(s[nt][1] * inv0, s[nt][0] * inv0);
        ph[nt][1] = packh(s[nt][3] * inv1, s[nt][2] * inv1);
    }
    ph[37][0] = ph[37][1] = 0u;

    // ---- AV (single pass) ----
    float o[8][4];
#pragma unroll
    for (int nt = 0; nt < 8; nt++)
#pragma unroll
        for (int r = 0; r < 4; r++) o[nt][r] = 0.f;

#pragma unroll
    for (int kc = 0; kc < 19; kc++) {
        uint32_t a[4] = { ph[2 * kc][0], ph[2 * kc][1],
                          ph[2 * kc + 1][0], ph[2 * kc + 1][1] };
        int vb0 = SV_ + qr * 156 + kc * 8 + qc;
#pragma unroll
        for (int nt = 0; nt < 8; nt++) {
            int vb = vb0 + nt * 1248;
            uint32_t bb[2] = { smw[vb], smw[vb + 4] };
            mma_f16(o[nt], a, bb);
        }
    }

    // ---- stage + store (token-major fp16) ----
    __syncthreads();
    float* Osm = (float*)smw;   // [128][68] = 34816 B < ATTN_SMEM
#pragma unroll
    for (int nt = 0; nt < 8; nt++) {
        int col = nt * 8 + qc * 2;
        int r0 = (w * 16 + qr) * 68;
        Osm[r0 + col]              = o[nt][0];
        Osm[r0 + col + 1]          = o[nt][1];
        Osm[r0 + 8 * 68 + col]     = o[nt][2];
        Osm[r0 + 8 * 68 + col + 1] = o[nt][3];
    }
    __syncthreads();
    for (int idx = t; idx < 8192; idx += 256) {
        int tok = idx >> 6, dc = idx & 63;
        g_aoT[((long)(b * 4096 + n0 + tok)) * 512 + hh * 64 + dc] =
            __float2half_rn(Osm[tok * 68 + dc]);
    }
}

// ---------------------------------------------------------------------------
// launcher
// ---------------------------------------------------------------------------
extern "C" void kernel_launch(void* const* d_in, const int* in_sizes, int n_in,
                              void* d_out, int out_size)
{
    const float* sem  = (const float*)d_in[0];
    const float* spa  = (const float*)d_in[1];
    const float* x    = (const float*)d_in[2];
    const float* wq   = (const float*)d_in[3];
    const float* wdw  = (const float*)d_in[4];
    const float* lng  = (const float*)d_in[5];
    const float* lnb  = (const float*)d_in[6];
    const float* wpw  = (const float*)d_in[7];
    const float* wout = (const float*)d_in[8];
    float* out = (float*)d_out;

    cudaFuncSetAttribute(gemm_mma, cudaFuncAttributeMaxDynamicSharedMemorySize, GSM);
    cudaFuncSetAttribute(attn_kernel, cudaFuncAttributeMaxDynamicSharedMemorySize, ATTN_SMEM);

    prep_w<<<3072, 256>>>(wq, wpw, wout);
    transpose_split<<<dim3(128, 16, 8), dim3(32, 8)>>>(sem);
    dw_kernel<<<dim3(512, 8), 128>>>(spa, wdw, 0);
    dw_kernel<<<dim3(512, 8), 128>>>(x,   wdw, 1);
    ln_kernel<<<dim3(289, 8), 512>>>(lng, lnb, 0);
    ln_kernel<<<dim3(289, 8), 512>>>(lng, lnb, 1);

    gemm_mma<<<dim3(32, 4, 8), 256, GSM>>>(0, 0, 0, nullptr, HWQ);   // q
    gemm_mma<<<dim3(3, 4, 8), 256, GSM>>>(1, 1, 1, nullptr, NKV);    // k
    gemm_mma<<<dim3(3, 4, 8), 256, GSM>>>(2, 1, 2, nullptr, NKV);    // v
    attn_kernel<<<dim3(32, 64), 256, ATTN_SMEM>>>();
    gemm_mma<<<dim3(32, 4, 8), 256, GSM>>>(3, 2, 3, out, HWQ);       // out
}